// round 2
// baseline (speedup 1.0000x reference)
#include <cuda_runtime.h>
#include <stdint.h>

// ============================================================================
// SparseGradLinear:
//   h   = x @ U^T                      [32768, 768]
//   h   = (|h| > 1e-3) ? h : 0
//   out = h @ (VT @ weight)^T + bias   [32768, 768]
//
// W2 = VT @ weight fuses GEMM2+GEMM3 of the reference (linear ops commute),
// cutting FLOPs from 116G to 78G.
// ============================================================================

#define DIM 768
#define M_TOTAL 32768

// Scratch (no cudaMalloc allowed): h buffer + fused weight matrix.
__device__ float g_h[(size_t)M_TOTAL * DIM];
__device__ float g_w2[DIM * DIM];

// ---- packed f32x2 helpers (full-rate fp32 FMA on sm_103a) ----
__device__ __forceinline__ unsigned long long pack_dup(float v) {
    unsigned long long r;
    asm("mov.b64 %0, {%1, %1};" : "=l"(r) : "f"(v));
    return r;
}
__device__ __forceinline__ void fma_f32x2(unsigned long long& d,
                                          unsigned long long a,
                                          unsigned long long b) {
    asm("fma.rn.f32x2 %0, %1, %2, %0;" : "+l"(d) : "l"(a), "l"(b));
}

// ============================================================================
// NT GEMM: C[M,N] = A[M,K] @ B[N,K]^T   (both operands K-contiguous)
// Tile 128x128x8, 256 threads, 8x8 per thread, f32x2 packed accumulation.
// MODE 0: epilogue thresholds |v| > 1e-3 (writes h)
// MODE 1: epilogue adds bias[col]       (writes out)
// ============================================================================
template <int MODE>
__global__ __launch_bounds__(256, 2)
void gemm_nt(const float* __restrict__ A, const float* __restrict__ B,
             float* __restrict__ C, const float* __restrict__ bias,
             int M, int N, int K)
{
    constexpr int BK = 8;
    constexpr int LDS = 136;  // padded row stride (floats), 16B-aligned rows

    __shared__ float As[BK * LDS];
    __shared__ float Bs[BK * LDS];

    const int bm = blockIdx.x * 128;
    const int bn = blockIdx.y * 128;

    const int t  = threadIdx.x;
    const int tx = t & 15;   // 0..15 -> col group (8 cols)
    const int ty = t >> 4;   // 0..15 -> row group (8 rows)

    // Loader mapping: each thread loads one float4 of A and one of B per k-tile.
    const int lr = t >> 1;          // 0..127 row within tile
    const int lk = (t & 1) * 4;     // 0 or 4

    const float* Ag = A + (size_t)(bm + lr) * K + lk;
    const float* Bg = B + (size_t)(bn + lr) * K + lk;

    unsigned long long acc[8][4];
#pragma unroll
    for (int i = 0; i < 8; i++)
#pragma unroll
        for (int j = 0; j < 4; j++) acc[i][j] = 0ull;

    for (int k0 = 0; k0 < K; k0 += BK) {
        float4 av = *(const float4*)(Ag + k0);
        float4 bv = *(const float4*)(Bg + k0);

        As[(lk + 0) * LDS + lr] = av.x;
        As[(lk + 1) * LDS + lr] = av.y;
        As[(lk + 2) * LDS + lr] = av.z;
        As[(lk + 3) * LDS + lr] = av.w;
        Bs[(lk + 0) * LDS + lr] = bv.x;
        Bs[(lk + 1) * LDS + lr] = bv.y;
        Bs[(lk + 2) * LDS + lr] = bv.z;
        Bs[(lk + 3) * LDS + lr] = bv.w;
        __syncthreads();

#pragma unroll
        for (int k = 0; k < BK; k++) {
            // a: 8 rows for this thread (duplicated into both f32x2 lanes)
            float4 a0 = *(const float4*)&As[k * LDS + ty * 8];
            float4 a1 = *(const float4*)&As[k * LDS + ty * 8 + 4];
            // b: 8 cols, already adjacent in smem -> natural f32x2 pairs
            ulonglong2 bq0 = *(const ulonglong2*)&Bs[k * LDS + tx * 8];
            ulonglong2 bq1 = *(const ulonglong2*)&Bs[k * LDS + tx * 8 + 4];

            unsigned long long ad[8];
            ad[0] = pack_dup(a0.x); ad[1] = pack_dup(a0.y);
            ad[2] = pack_dup(a0.z); ad[3] = pack_dup(a0.w);
            ad[4] = pack_dup(a1.x); ad[5] = pack_dup(a1.y);
            ad[6] = pack_dup(a1.z); ad[7] = pack_dup(a1.w);

            unsigned long long bp[4];
            bp[0] = bq0.x; bp[1] = bq0.y; bp[2] = bq1.x; bp[3] = bq1.y;

#pragma unroll
            for (int i = 0; i < 8; i++) {
#pragma unroll
                for (int j = 0; j < 4; j++) {
                    fma_f32x2(acc[i][j], ad[i], bp[j]);
                }
            }
        }
        __syncthreads();
    }

    // Epilogue
#pragma unroll
    for (int i = 0; i < 8; i++) {
        const int row = bm + ty * 8 + i;
        float* crow = C + (size_t)row * N + bn + tx * 8;
#pragma unroll
        for (int j = 0; j < 4; j++) {
            float2 v = *reinterpret_cast<float2*>(&acc[i][j]);
            if (MODE == 0) {
                v.x = (fabsf(v.x) > 1e-3f) ? v.x : 0.0f;
                v.y = (fabsf(v.y) > 1e-3f) ? v.y : 0.0f;
            } else {
                const float2 bb = *(const float2*)&bias[bn + tx * 8 + j * 2];
                v.x += bb.x;
                v.y += bb.y;
            }
            *(float2*)(crow + j * 2) = v;
        }
    }
}

// ============================================================================
// Small NN GEMM: W2[p,c] = sum_o VT[p,o] * weight[o,c]   (768x768x768)
// Tile 64x64x16, 256 threads, 4x4 per thread. ~0.9 GFLOP, not on critical path.
// ============================================================================
__global__ __launch_bounds__(256)
void gemm_nn_small(const float* __restrict__ A, const float* __restrict__ B,
                   float* __restrict__ C, int N, int K)
{
    constexpr int BK = 16;
    __shared__ float As[BK][68];  // transposed: As[o][p], padded
    __shared__ float Bs[BK][64];

    const int bp = blockIdx.y * 64;
    const int bc = blockIdx.x * 64;

    const int t  = threadIdx.x;
    const int tx = t & 15;
    const int ty = t >> 4;

    float acc[4][4] = {};

    for (int k0 = 0; k0 < K; k0 += BK) {
        // A tile: 64 rows(p) x 16(o); thread -> row t>>2, o offset (t&3)*4
        {
            const int r = t >> 2;
            const int o4 = (t & 3) * 4;
            float4 av = *(const float4*)(A + (size_t)(bp + r) * K + k0 + o4);
            As[o4 + 0][r] = av.x;
            As[o4 + 1][r] = av.y;
            As[o4 + 2][r] = av.z;
            As[o4 + 3][r] = av.w;
        }
        // B tile: 16 rows(o) x 64 cols(c); thread -> o = t>>4, c offset (t&15)*4
        {
            const int o  = t >> 4;
            const int c4 = (t & 15) * 4;
            float4 bv = *(const float4*)(B + (size_t)(k0 + o) * N + bc + c4);
            *(float4*)&Bs[o][c4] = bv;
        }
        __syncthreads();

#pragma unroll
        for (int o = 0; o < BK; o++) {
            float a[4], b[4];
#pragma unroll
            for (int i = 0; i < 4; i++) a[i] = As[o][ty * 4 + i];
#pragma unroll
            for (int j = 0; j < 4; j++) b[j] = Bs[o][tx * 4 + j];
#pragma unroll
            for (int i = 0; i < 4; i++)
#pragma unroll
                for (int j = 0; j < 4; j++) acc[i][j] += a[i] * b[j];
        }
        __syncthreads();
    }

#pragma unroll
    for (int i = 0; i < 4; i++)
#pragma unroll
        for (int j = 0; j < 4; j++)
            C[(size_t)(bp + ty * 4 + i) * N + bc + tx * 4 + j] = acc[i][j];
}

// ============================================================================
// kernel_launch
// inputs (metadata order): x[32768*768], weight[768*768], bias[768],
//                          U[768*768], VT[768*768]; output float32 [32768*768]
// ============================================================================
extern "C" void kernel_launch(void* const* d_in, const int* in_sizes, int n_in,
                              void* d_out, int out_size)
{
    const float* x      = (const float*)d_in[0];
    const float* weight = (const float*)d_in[1];
    const float* bias   = (const float*)d_in[2];
    const float* U      = (const float*)d_in[3];
    const float* VT     = (const float*)d_in[4];
    float* out          = (float*)d_out;

    float *h_ptr, *w2_ptr;
    cudaGetSymbolAddress((void**)&h_ptr, g_h);
    cudaGetSymbolAddress((void**)&w2_ptr, g_w2);

    const int M = in_sizes[0] / DIM;  // 32768
    const int N = DIM, K = DIM;

    // W2 = VT @ weight  (fuses the last two reference GEMMs)
    gemm_nn_small<<<dim3(DIM / 64, DIM / 64), 256>>>(VT, weight, w2_ptr, DIM, DIM);
    // h = threshold(x @ U^T)
    gemm_nt<0><<<dim3(M / 128, N / 128), 256>>>(x, U, h_ptr, nullptr, M, N, K);
    // out = h @ W2^T + bias
    gemm_nt<1><<<dim3(M / 128, N / 128), 256>>>(h_ptr, w2_ptr, out, bias, M, N, K);
}

// round 4
// speedup vs baseline: 1.9079x; 1.9079x over previous
#include <cuda_runtime.h>
#include <cuda_bf16.h>
#include <stdint.h>

// ============================================================================
// SparseGradLinear via base-ISA tensor cores (ldmatrix + mma.sync bf16):
//   h   = threshold(x @ U^T)           [32768, 768]
//   out = h @ (VT @ weight)^T + bias   [32768, 768]
// Split precision: A=A0+A1, B=B0+B1 (bf16 hi/lo); C = A0B0+A0B1+A1B0 in fp32.
// (tcgen05 is unavailable: harness PTX target is sm_103 without the 'a' set.)
// ============================================================================

#define DIM    768
#define MROWS  32768

__device__ __nv_bfloat16 g_x0[(size_t)MROWS * DIM];
__device__ __nv_bfloat16 g_x1[(size_t)MROWS * DIM];
__device__ __nv_bfloat16 g_h0[(size_t)MROWS * DIM];
__device__ __nv_bfloat16 g_h1[(size_t)MROWS * DIM];
__device__ __nv_bfloat16 g_u0[DIM * DIM];
__device__ __nv_bfloat16 g_u1[DIM * DIM];
__device__ __nv_bfloat16 g_w20[DIM * DIM];
__device__ __nv_bfloat16 g_w21[DIM * DIM];

// ---- helpers ----
__device__ __forceinline__ uint32_t smem_u32(const void* p) {
    uint32_t a;
    asm("{ .reg .u64 t; cvta.to.shared.u64 t, %1; cvt.u32.u64 %0, t; }"
        : "=r"(a) : "l"(p));
    return a;
}
__device__ __forceinline__ void cp16(uint32_t dst, const void* src) {
    asm volatile("cp.async.cg.shared.global [%0], [%1], 16;" :: "r"(dst), "l"(src));
}
__device__ __forceinline__ void ldsm4(uint32_t* r, uint32_t addr) {
    asm volatile("ldmatrix.sync.aligned.m8n8.x4.shared.b16 {%0,%1,%2,%3}, [%4];"
                 : "=r"(r[0]), "=r"(r[1]), "=r"(r[2]), "=r"(r[3]) : "r"(addr));
}
__device__ __forceinline__ void mma16816(float* d, const uint32_t* a,
                                         uint32_t b0, uint32_t b1) {
    asm volatile(
        "mma.sync.aligned.m16n8k16.row.col.f32.bf16.bf16.f32 "
        "{%0,%1,%2,%3}, {%4,%5,%6,%7}, {%8,%9}, {%0,%1,%2,%3};"
        : "+f"(d[0]), "+f"(d[1]), "+f"(d[2]), "+f"(d[3])
        : "r"(a[0]), "r"(a[1]), "r"(a[2]), "r"(a[3]), "r"(b0), "r"(b1));
}
__device__ __forceinline__ void split_bf16(float v, __nv_bfloat16& hi, __nv_bfloat16& lo) {
    hi = __float2bfloat16_rn(v);
    lo = __float2bfloat16_rn(v - __bfloat162float(hi));
}

// ============================================================================
// Tensor-core NT GEMM: C[M,N] = (A0+A1) @ (B0+B1)^T, all K-contiguous.
// CTA 128x128, BK=32, 256 thr (8 warps, 2m x 4n grid, warp tile 64x32),
// 3-stage cp.async pipeline; 4 operand matrices per stage, 80B padded rows.
// MODE 0: threshold |v|>1e-3, re-split to bf16 H0/H1.  MODE 1: +bias, fp32.
// ============================================================================
#define NCHUNK 24            // 768 / 32
#define BKB    64            // bytes of K per chunk-row (32 bf16)
#define ROWB   80            // padded row stride in bytes
#define MATB   (128 * ROWB)  // 10240 per operand tile
#define STAGEB (4 * MATB)    // 40960
#define NSTAGE 3
#define GEMM_SMEM (NSTAGE * STAGEB)

template <int MODE>
__global__ void __launch_bounds__(256, 1)
gemm_mma(const __nv_bfloat16* __restrict__ A0, const __nv_bfloat16* __restrict__ A1,
         const __nv_bfloat16* __restrict__ B0, const __nv_bfloat16* __restrict__ B1,
         float* __restrict__ outF,
         __nv_bfloat16* __restrict__ H0, __nv_bfloat16* __restrict__ H1,
         const float* __restrict__ bias)
{
    extern __shared__ char smem[];
    const uint32_t sb = smem_u32(smem);

    const int tid  = threadIdx.x;
    const int lane = tid & 31;
    const int wid  = tid >> 5;
    const int wm   = wid >> 2;      // 0..1 -> 64-row band
    const int wn   = wid & 3;       // 0..3 -> 32-col band
    const int bm   = blockIdx.y * 128;
    const int bn   = blockIdx.x * 128;

    // ---- loader mapping: thread -> (row, 32B-half of the 64B chunk-row) ----
    const int lrow = tid >> 1;
    const int lqB  = (tid & 1) * 32;         // byte offset within row
    const char* gA0 = (const char*)(A0 + (size_t)(bm + lrow) * DIM) + lqB;
    const char* gA1 = (const char*)(A1 + (size_t)(bm + lrow) * DIM) + lqB;
    const char* gB0 = (const char*)(B0 + (size_t)(bn + lrow) * DIM) + lqB;
    const char* gB1 = (const char*)(B1 + (size_t)(bn + lrow) * DIM) + lqB;
    const uint32_t sdst = lrow * ROWB + lqB;

#define LOAD_CHUNK(c) do { \
    const uint32_t _st = sb + ((c) % NSTAGE) * STAGEB + sdst; \
    const int _kb = (c) * BKB; \
    cp16(_st,                gA0 + _kb); cp16(_st + 16,            gA0 + _kb + 16); \
    cp16(_st + MATB,         gA1 + _kb); cp16(_st + MATB + 16,     gA1 + _kb + 16); \
    cp16(_st + 2 * MATB,     gB0 + _kb); cp16(_st + 2 * MATB + 16, gB0 + _kb + 16); \
    cp16(_st + 3 * MATB,     gB1 + _kb); cp16(_st + 3 * MATB + 16, gB1 + _kb + 16); \
    asm volatile("cp.async.commit_group;" ::: "memory"); \
} while (0)

    // ---- ldmatrix lane address components ----
    const int lr8 = ((lane >> 3) & 1) * 8 + (lane & 7);  // row within 16
    const int lcb = ((lane >> 4) & 1) * 16;              // 16B col half
    const uint32_t aRow = wm * 64 + lr8;                 // + mt*16
    const uint32_t bRow = wn * 32 + lr8;                 // + ng*16

    float acc[4][4][4];
#pragma unroll
    for (int i = 0; i < 4; i++)
#pragma unroll
        for (int j = 0; j < 4; j++)
#pragma unroll
            for (int k = 0; k < 4; k++) acc[i][j][k] = 0.0f;

    LOAD_CHUNK(0);
    LOAD_CHUNK(1);

    for (int c = 0; c < NCHUNK; c++) {
        if (c + 1 < NCHUNK) asm volatile("cp.async.wait_group 1;" ::: "memory");
        else                asm volatile("cp.async.wait_group 0;" ::: "memory");
        __syncthreads();   // chunk c visible; all warps done with chunk c-1

        if (c + 2 < NCHUNK) LOAD_CHUNK(c + 2);  // overwrites stage of c-1

        const uint32_t stg = sb + (c % NSTAGE) * STAGEB;
#pragma unroll
        for (int ks = 0; ks < 2; ks++) {
            uint32_t af0[4][4], af1[4][4];
#pragma unroll
            for (int mt = 0; mt < 4; mt++) {
                const uint32_t ra = stg + (aRow + mt * 16) * ROWB + ks * 32 + lcb;
                ldsm4(af0[mt], ra);
                ldsm4(af1[mt], ra + MATB);
            }
            uint32_t bf0[2][4], bf1[2][4];
#pragma unroll
            for (int ng = 0; ng < 2; ng++) {
                const uint32_t rb = stg + 2 * MATB + (bRow + ng * 16) * ROWB + ks * 32 + lcb;
                ldsm4(bf0[ng], rb);
                ldsm4(bf1[ng], rb + MATB);
            }
#pragma unroll
            for (int mt = 0; mt < 4; mt++) {
#pragma unroll
                for (int nt = 0; nt < 4; nt++) {
                    const int ng = nt >> 1, p = nt & 1;
                    mma16816(acc[mt][nt], af0[mt], bf0[ng][p], bf0[ng][p + 2]);
                    mma16816(acc[mt][nt], af0[mt], bf1[ng][p], bf1[ng][p + 2]);
                    mma16816(acc[mt][nt], af1[mt], bf0[ng][p], bf0[ng][p + 2]);
                }
            }
        }
    }

    // ---- epilogue ----
    const int r0 = bm + wm * 64 + (lane >> 2);
    const int c0 = bn + wn * 32 + (lane & 3) * 2;
#pragma unroll
    for (int mt = 0; mt < 4; mt++) {
#pragma unroll
        for (int nt = 0; nt < 4; nt++) {
            const int col = c0 + nt * 8;
#pragma unroll
            for (int half = 0; half < 2; half++) {   // d0,d1 then d2,d3 (+8 rows)
                const int row = r0 + mt * 16 + half * 8;
                float vx = acc[mt][nt][half * 2];
                float vy = acc[mt][nt][half * 2 + 1];
                if (MODE == 0) {
                    vx = (fabsf(vx) > 1e-3f) ? vx : 0.0f;
                    vy = (fabsf(vy) > 1e-3f) ? vy : 0.0f;
                    __nv_bfloat162 hi, lo;
                    split_bf16(vx, hi.x, lo.x);
                    split_bf16(vy, hi.y, lo.y);
                    const size_t idx = (size_t)row * DIM + col;
                    *(__nv_bfloat162*)(H0 + idx) = hi;
                    *(__nv_bfloat162*)(H1 + idx) = lo;
                } else {
                    const float2 bb = *(const float2*)&bias[col];
                    float2 v = make_float2(vx + bb.x, vy + bb.y);
                    *(float2*)(outF + (size_t)row * DIM + col) = v;
                }
            }
        }
    }
}

// ============================================================================
// Elementwise fp32 -> (bf16 hi, bf16 lo) split.
// ============================================================================
__global__ void split_kernel(const float4* __restrict__ src,
                             __nv_bfloat16* __restrict__ d0,
                             __nv_bfloat16* __restrict__ d1, int n4)
{
    int i = blockIdx.x * blockDim.x + threadIdx.x;
    if (i >= n4) return;
    float4 v = src[i];
    __nv_bfloat162 h0, h1, l0, l1;
    split_bf16(v.x, h0.x, l0.x);
    split_bf16(v.y, h0.y, l0.y);
    split_bf16(v.z, h1.x, l1.x);
    split_bf16(v.w, h1.y, l1.y);
    __nv_bfloat162* p0 = (__nv_bfloat162*)(d0 + (size_t)i * 4);
    __nv_bfloat162* p1 = (__nv_bfloat162*)(d1 + (size_t)i * 4);
    p0[0] = h0; p0[1] = h1;
    p1[0] = l0; p1[1] = l1;
}

// ============================================================================
// Small fp32 NN GEMM: W2 = VT @ weight, epilogue splits to bf16 hi/lo.
// ============================================================================
__global__ void __launch_bounds__(256)
gemm_nn_small(const float* __restrict__ A, const float* __restrict__ B,
              __nv_bfloat16* __restrict__ C0, __nv_bfloat16* __restrict__ C1,
              int N, int K)
{
    constexpr int BK = 16;
    __shared__ float As[BK][68];
    __shared__ float Bs[BK][64];

    const int bp = blockIdx.y * 64;
    const int bc = blockIdx.x * 64;
    const int t  = threadIdx.x;
    const int tx = t & 15;
    const int ty = t >> 4;

    float acc[4][4] = {};

    for (int k0 = 0; k0 < K; k0 += BK) {
        {
            const int r = t >> 2;
            const int o4 = (t & 3) * 4;
            float4 av = *(const float4*)(A + (size_t)(bp + r) * K + k0 + o4);
            As[o4 + 0][r] = av.x; As[o4 + 1][r] = av.y;
            As[o4 + 2][r] = av.z; As[o4 + 3][r] = av.w;
        }
        {
            const int o  = t >> 4;
            const int c4 = (t & 15) * 4;
            *(float4*)&Bs[o][c4] = *(const float4*)(B + (size_t)(k0 + o) * N + bc + c4);
        }
        __syncthreads();
#pragma unroll
        for (int o = 0; o < BK; o++) {
            float a[4], b[4];
#pragma unroll
            for (int i = 0; i < 4; i++) a[i] = As[o][ty * 4 + i];
#pragma unroll
            for (int j = 0; j < 4; j++) b[j] = Bs[o][tx * 4 + j];
#pragma unroll
            for (int i = 0; i < 4; i++)
#pragma unroll
                for (int j = 0; j < 4; j++) acc[i][j] += a[i] * b[j];
        }
        __syncthreads();
    }

#pragma unroll
    for (int i = 0; i < 4; i++)
#pragma unroll
        for (int j = 0; j < 4; j++) {
            __nv_bfloat16 hi, lo;
            split_bf16(acc[i][j], hi, lo);
            const size_t idx = (size_t)(bp + ty * 4 + i) * N + bc + tx * 4 + j;
            C0[idx] = hi;
            C1[idx] = lo;
        }
}

// ============================================================================
// kernel_launch — inputs: x, weight, bias, U, VT; output fp32 [32768,768]
// ============================================================================
extern "C" void kernel_launch(void* const* d_in, const int* in_sizes, int n_in,
                              void* d_out, int out_size)
{
    const float* x      = (const float*)d_in[0];
    const float* weight = (const float*)d_in[1];
    const float* bias   = (const float*)d_in[2];
    const float* U      = (const float*)d_in[3];
    const float* VT     = (const float*)d_in[4];
    float* out          = (float*)d_out;

    __nv_bfloat16 *x0, *x1, *h0, *h1, *u0, *u1, *w20, *w21;
    cudaGetSymbolAddress((void**)&x0,  g_x0);
    cudaGetSymbolAddress((void**)&x1,  g_x1);
    cudaGetSymbolAddress((void**)&h0,  g_h0);
    cudaGetSymbolAddress((void**)&h1,  g_h1);
    cudaGetSymbolAddress((void**)&u0,  g_u0);
    cudaGetSymbolAddress((void**)&u1,  g_u1);
    cudaGetSymbolAddress((void**)&w20, g_w20);
    cudaGetSymbolAddress((void**)&w21, g_w21);

    cudaFuncSetAttribute(gemm_mma<0>, cudaFuncAttributeMaxDynamicSharedMemorySize, GEMM_SMEM);
    cudaFuncSetAttribute(gemm_mma<1>, cudaFuncAttributeMaxDynamicSharedMemorySize, GEMM_SMEM);

    const int M = in_sizes[0] / DIM;   // 32768

    {
        int n4 = M * DIM / 4;
        split_kernel<<<(n4 + 255) / 256, 256>>>((const float4*)x, x0, x1, n4);
    }
    {
        int n4 = DIM * DIM / 4;
        split_kernel<<<(n4 + 255) / 256, 256>>>((const float4*)U, u0, u1, n4);
    }
    gemm_nn_small<<<dim3(DIM / 64, DIM / 64), 256>>>(VT, weight, w20, w21, DIM, DIM);

    // GEMM1: h = threshold(x @ U^T) -> h0,h1
    gemm_mma<0><<<dim3(DIM / 128, M / 128), 256, GEMM_SMEM>>>(
        x0, x1, u0, u1, nullptr, h0, h1, nullptr);
    // GEMM2: out = h @ W2^T + bias
    gemm_mma<1><<<dim3(DIM / 128, M / 128), 256, GEMM_SMEM>>>(
        h0, h1, w20, w21, out, nullptr, nullptr, bias);
}

// round 5
// speedup vs baseline: 2.1081x; 1.1049x over previous
#include <cuda_runtime.h>
#include <cuda_bf16.h>
#include <stdint.h>

// ============================================================================
// SparseGradLinear via base-ISA tensor cores (ldmatrix + mma.sync bf16):
//   h   = threshold(x @ U^T)           [32768, 768]
//   out = h @ (VT @ weight)^T + bias   [32768, 768]
// Split precision: A=A0+A1, B=B0+B1 (bf16 hi/lo); C = A0B0+A0B1+A1B0 in fp32.
// R5: 2-stage pipeline (80KB smem) -> 2 CTAs/SM for latency hiding.
// ============================================================================

#define DIM    768
#define MROWS  32768

__device__ __nv_bfloat16 g_x0[(size_t)MROWS * DIM];
__device__ __nv_bfloat16 g_x1[(size_t)MROWS * DIM];
__device__ __nv_bfloat16 g_h0[(size_t)MROWS * DIM];
__device__ __nv_bfloat16 g_h1[(size_t)MROWS * DIM];
__device__ __nv_bfloat16 g_u0[DIM * DIM];
__device__ __nv_bfloat16 g_u1[DIM * DIM];
__device__ __nv_bfloat16 g_w20[DIM * DIM];
__device__ __nv_bfloat16 g_w21[DIM * DIM];

// ---- helpers ----
__device__ __forceinline__ uint32_t smem_u32(const void* p) {
    uint32_t a;
    asm("{ .reg .u64 t; cvta.to.shared.u64 t, %1; cvt.u32.u64 %0, t; }"
        : "=r"(a) : "l"(p));
    return a;
}
__device__ __forceinline__ void cp16(uint32_t dst, const void* src) {
    asm volatile("cp.async.cg.shared.global [%0], [%1], 16;" :: "r"(dst), "l"(src));
}
__device__ __forceinline__ void ldsm4(uint32_t* r, uint32_t addr) {
    asm volatile("ldmatrix.sync.aligned.m8n8.x4.shared.b16 {%0,%1,%2,%3}, [%4];"
                 : "=r"(r[0]), "=r"(r[1]), "=r"(r[2]), "=r"(r[3]) : "r"(addr));
}
__device__ __forceinline__ void mma16816(float* d, const uint32_t* a,
                                         uint32_t b0, uint32_t b1) {
    asm volatile(
        "mma.sync.aligned.m16n8k16.row.col.f32.bf16.bf16.f32 "
        "{%0,%1,%2,%3}, {%4,%5,%6,%7}, {%8,%9}, {%0,%1,%2,%3};"
        : "+f"(d[0]), "+f"(d[1]), "+f"(d[2]), "+f"(d[3])
        : "r"(a[0]), "r"(a[1]), "r"(a[2]), "r"(a[3]), "r"(b0), "r"(b1));
}
__device__ __forceinline__ void split_bf16(float v, __nv_bfloat16& hi, __nv_bfloat16& lo) {
    hi = __float2bfloat16_rn(v);
    lo = __float2bfloat16_rn(v - __bfloat162float(hi));
}

// ============================================================================
// Tensor-core NT GEMM: C[M,N] = (A0+A1) @ (B0+B1)^T, all K-contiguous.
// CTA 128x128, BK=32, 256 thr (8 warps, 2m x 4n grid, warp tile 64x32),
// 2-stage cp.async pipeline; 4 operand matrices per stage, 80B padded rows.
// MODE 0: threshold |v|>1e-3, re-split to bf16 H0/H1.  MODE 1: +bias, fp32.
// ============================================================================
#define NCHUNK 24            // 768 / 32
#define BKB    64            // bytes of K per chunk-row (32 bf16)
#define ROWB   80            // padded row stride in bytes
#define MATB   (128 * ROWB)  // 10240 per operand tile
#define STAGEB (4 * MATB)    // 40960
#define NSTAGE 2
#define GEMM_SMEM (NSTAGE * STAGEB)   // 81920 -> 2 CTAs/SM

template <int MODE>
__global__ void __launch_bounds__(256, 2)
gemm_mma(const __nv_bfloat16* __restrict__ A0, const __nv_bfloat16* __restrict__ A1,
         const __nv_bfloat16* __restrict__ B0, const __nv_bfloat16* __restrict__ B1,
         float* __restrict__ outF,
         __nv_bfloat16* __restrict__ H0, __nv_bfloat16* __restrict__ H1,
         const float* __restrict__ bias)
{
    extern __shared__ char smem[];
    const uint32_t sb = smem_u32(smem);

    const int tid  = threadIdx.x;
    const int lane = tid & 31;
    const int wid  = tid >> 5;
    const int wm   = wid >> 2;      // 0..1 -> 64-row band
    const int wn   = wid & 3;       // 0..3 -> 32-col band
    const int bm   = blockIdx.y * 128;
    const int bn   = blockIdx.x * 128;

    // ---- loader mapping: thread -> (row, 32B-half of the 64B chunk-row) ----
    const int lrow = tid >> 1;
    const int lqB  = (tid & 1) * 32;
    const char* gA0 = (const char*)(A0 + (size_t)(bm + lrow) * DIM) + lqB;
    const char* gA1 = (const char*)(A1 + (size_t)(bm + lrow) * DIM) + lqB;
    const char* gB0 = (const char*)(B0 + (size_t)(bn + lrow) * DIM) + lqB;
    const char* gB1 = (const char*)(B1 + (size_t)(bn + lrow) * DIM) + lqB;
    const uint32_t sdst = lrow * ROWB + lqB;

#define LOAD_CHUNK(c) do { \
    const uint32_t _st = sb + ((c) % NSTAGE) * STAGEB + sdst; \
    const int _kb = (c) * BKB; \
    cp16(_st,                gA0 + _kb); cp16(_st + 16,            gA0 + _kb + 16); \
    cp16(_st + MATB,         gA1 + _kb); cp16(_st + MATB + 16,     gA1 + _kb + 16); \
    cp16(_st + 2 * MATB,     gB0 + _kb); cp16(_st + 2 * MATB + 16, gB0 + _kb + 16); \
    cp16(_st + 3 * MATB,     gB1 + _kb); cp16(_st + 3 * MATB + 16, gB1 + _kb + 16); \
    asm volatile("cp.async.commit_group;" ::: "memory"); \
} while (0)

    // ---- ldmatrix lane address components ----
    const int lr8 = ((lane >> 3) & 1) * 8 + (lane & 7);
    const int lcb = ((lane >> 4) & 1) * 16;
    const uint32_t aRow = wm * 64 + lr8;
    const uint32_t bRow = wn * 32 + lr8;

    float acc[4][4][4];
#pragma unroll
    for (int i = 0; i < 4; i++)
#pragma unroll
        for (int j = 0; j < 4; j++)
#pragma unroll
            for (int k = 0; k < 4; k++) acc[i][j][k] = 0.0f;

    LOAD_CHUNK(0);
    LOAD_CHUNK(1);

    for (int c = 0; c < NCHUNK; c++) {
        if (c + 1 < NCHUNK) asm volatile("cp.async.wait_group 1;" ::: "memory");
        else                asm volatile("cp.async.wait_group 0;" ::: "memory");
        __syncthreads();   // chunk c resident CTA-wide

        const uint32_t stg = sb + (c % NSTAGE) * STAGEB;
#pragma unroll
        for (int ks = 0; ks < 2; ks++) {
            uint32_t af0[4][4], af1[4][4];
#pragma unroll
            for (int mt = 0; mt < 4; mt++) {
                const uint32_t ra = stg + (aRow + mt * 16) * ROWB + ks * 32 + lcb;
                ldsm4(af0[mt], ra);
                ldsm4(af1[mt], ra + MATB);
            }
            uint32_t bf0[2][4], bf1[2][4];
#pragma unroll
            for (int ng = 0; ng < 2; ng++) {
                const uint32_t rb = stg + 2 * MATB + (bRow + ng * 16) * ROWB + ks * 32 + lcb;
                ldsm4(bf0[ng], rb);
                ldsm4(bf1[ng], rb + MATB);
            }
#pragma unroll
            for (int mt = 0; mt < 4; mt++) {
#pragma unroll
                for (int nt = 0; nt < 4; nt++) {
                    const int ng = nt >> 1, p = nt & 1;
                    mma16816(acc[mt][nt], af0[mt], bf0[ng][p], bf0[ng][p + 2]);
                    mma16816(acc[mt][nt], af0[mt], bf1[ng][p], bf1[ng][p + 2]);
                    mma16816(acc[mt][nt], af1[mt], bf0[ng][p], bf0[ng][p + 2]);
                }
            }
        }

        // Stage reuse: all warps must finish reading chunk c before its stage
        // is overwritten by chunk c+2 (loads overlap compute of chunk c+1).
        if (c + 2 < NCHUNK) {
            __syncthreads();
            LOAD_CHUNK(c + 2);
        }
    }

    // ---- epilogue ----
    const int r0 = bm + wm * 64 + (lane >> 2);
    const int c0 = bn + wn * 32 + (lane & 3) * 2;
#pragma unroll
    for (int mt = 0; mt < 4; mt++) {
#pragma unroll
        for (int nt = 0; nt < 4; nt++) {
            const int col = c0 + nt * 8;
#pragma unroll
            for (int half = 0; half < 2; half++) {
                const int row = r0 + mt * 16 + half * 8;
                float vx = acc[mt][nt][half * 2];
                float vy = acc[mt][nt][half * 2 + 1];
                if (MODE == 0) {
                    vx = (fabsf(vx) > 1e-3f) ? vx : 0.0f;
                    vy = (fabsf(vy) > 1e-3f) ? vy : 0.0f;
                    __nv_bfloat162 hi, lo;
                    split_bf16(vx, hi.x, lo.x);
                    split_bf16(vy, hi.y, lo.y);
                    const size_t idx = (size_t)row * DIM + col;
                    *(__nv_bfloat162*)(H0 + idx) = hi;
                    *(__nv_bfloat162*)(H1 + idx) = lo;
                } else {
                    const float2 bb = *(const float2*)&bias[col];
                    float2 v = make_float2(vx + bb.x, vy + bb.y);
                    *(float2*)(outF + (size_t)row * DIM + col) = v;
                }
            }
        }
    }
}

// ============================================================================
// Elementwise fp32 -> (bf16 hi, bf16 lo) split.
// ============================================================================
__global__ void split_kernel(const float4* __restrict__ src,
                             __nv_bfloat16* __restrict__ d0,
                             __nv_bfloat16* __restrict__ d1, int n4)
{
    int i = blockIdx.x * blockDim.x + threadIdx.x;
    if (i >= n4) return;
    float4 v = src[i];
    __nv_bfloat162 h0, h1, l0, l1;
    split_bf16(v.x, h0.x, l0.x);
    split_bf16(v.y, h0.y, l0.y);
    split_bf16(v.z, h1.x, l1.x);
    split_bf16(v.w, h1.y, l1.y);
    __nv_bfloat162* p0 = (__nv_bfloat162*)(d0 + (size_t)i * 4);
    __nv_bfloat162* p1 = (__nv_bfloat162*)(d1 + (size_t)i * 4);
    p0[0] = h0; p0[1] = h1;
    p1[0] = l0; p1[1] = l1;
}

// ============================================================================
// Small fp32 NN GEMM: W2 = VT @ weight, epilogue splits to bf16 hi/lo.
// ============================================================================
__global__ void __launch_bounds__(256)
gemm_nn_small(const float* __restrict__ A, const float* __restrict__ B,
              __nv_bfloat16* __restrict__ C0, __nv_bfloat16* __restrict__ C1,
              int N, int K)
{
    constexpr int BK = 16;
    __shared__ float As[BK][68];
    __shared__ float Bs[BK][64];

    const int bp = blockIdx.y * 64;
    const int bc = blockIdx.x * 64;
    const int t  = threadIdx.x;
    const int tx = t & 15;
    const int ty = t >> 4;

    float acc[4][4] = {};

    for (int k0 = 0; k0 < K; k0 += BK) {
        {
            const int r = t >> 2;
            const int o4 = (t & 3) * 4;
            float4 av = *(const float4*)(A + (size_t)(bp + r) * K + k0 + o4);
            As[o4 + 0][r] = av.x; As[o4 + 1][r] = av.y;
            As[o4 + 2][r] = av.z; As[o4 + 3][r] = av.w;
        }
        {
            const int o  = t >> 4;
            const int c4 = (t & 15) * 4;
            *(float4*)&Bs[o][c4] = *(const float4*)(B + (size_t)(k0 + o) * N + bc + c4);
        }
        __syncthreads();
#pragma unroll
        for (int o = 0; o < BK; o++) {
            float a[4], b[4];
#pragma unroll
            for (int i = 0; i < 4; i++) a[i] = As[o][ty * 4 + i];
#pragma unroll
            for (int j = 0; j < 4; j++) b[j] = Bs[o][tx * 4 + j];
#pragma unroll
            for (int i = 0; i < 4; i++)
#pragma unroll
                for (int j = 0; j < 4; j++) acc[i][j] += a[i] * b[j];
        }
        __syncthreads();
    }

#pragma unroll
    for (int i = 0; i < 4; i++)
#pragma unroll
        for (int j = 0; j < 4; j++) {
            __nv_bfloat16 hi, lo;
            split_bf16(acc[i][j], hi, lo);
            const size_t idx = (size_t)(bp + ty * 4 + i) * N + bc + tx * 4 + j;
            C0[idx] = hi;
            C1[idx] = lo;
        }
}

// ============================================================================
// kernel_launch — inputs: x, weight, bias, U, VT; output fp32 [32768,768]
// ============================================================================
extern "C" void kernel_launch(void* const* d_in, const int* in_sizes, int n_in,
                              void* d_out, int out_size)
{
    const float* x      = (const float*)d_in[0];
    const float* weight = (const float*)d_in[1];
    const float* bias   = (const float*)d_in[2];
    const float* U      = (const float*)d_in[3];
    const float* VT     = (const float*)d_in[4];
    float* out          = (float*)d_out;

    __nv_bfloat16 *x0, *x1, *h0, *h1, *u0, *u1, *w20, *w21;
    cudaGetSymbolAddress((void**)&x0,  g_x0);
    cudaGetSymbolAddress((void**)&x1,  g_x1);
    cudaGetSymbolAddress((void**)&h0,  g_h0);
    cudaGetSymbolAddress((void**)&h1,  g_h1);
    cudaGetSymbolAddress((void**)&u0,  g_u0);
    cudaGetSymbolAddress((void**)&u1,  g_u1);
    cudaGetSymbolAddress((void**)&w20, g_w20);
    cudaGetSymbolAddress((void**)&w21, g_w21);

    cudaFuncSetAttribute(gemm_mma<0>, cudaFuncAttributeMaxDynamicSharedMemorySize, GEMM_SMEM);
    cudaFuncSetAttribute(gemm_mma<1>, cudaFuncAttributeMaxDynamicSharedMemorySize, GEMM_SMEM);

    const int M = in_sizes[0] / DIM;   // 32768

    {
        int n4 = M * DIM / 4;
        split_kernel<<<(n4 + 255) / 256, 256>>>((const float4*)x, x0, x1, n4);
    }
    {
        int n4 = DIM * DIM / 4;
        split_kernel<<<(n4 + 255) / 256, 256>>>((const float4*)U, u0, u1, n4);
    }
    gemm_nn_small<<<dim3(DIM / 64, DIM / 64), 256>>>(VT, weight, w20, w21, DIM, DIM);

    // GEMM1: h = threshold(x @ U^T) -> h0,h1
    gemm_mma<0><<<dim3(DIM / 128, M / 128), 256, GEMM_SMEM>>>(
        x0, x1, u0, u1, nullptr, h0, h1, nullptr);
    // GEMM2: out = h @ W2^T + bias
    gemm_mma<1><<<dim3(DIM / 128, M / 128), 256, GEMM_SMEM>>>(
        h0, h1, w20, w21, out, nullptr, nullptr, bias);
}

// round 6
// speedup vs baseline: 2.1883x; 1.0380x over previous
#include <cuda_runtime.h>
#include <cuda_bf16.h>
#include <stdint.h>

// ============================================================================
// SparseGradLinear via base-ISA tensor cores (ldmatrix + mma.sync bf16):
//   h   = threshold(x @ U^T)           [32768, 768]
//   out = h @ (VT @ weight)^T + bias   [32768, 768]
// Split precision: A=A0+A1, B=B0+B1 (bf16 hi/lo); C = A0B0+A0B1+A1B0 in fp32.
// R6: product-major MMA ordering (dependency-stall-free), split-K W2 prep.
// ============================================================================

#define DIM    768
#define MROWS  32768

__device__ __nv_bfloat16 g_x0[(size_t)MROWS * DIM];
__device__ __nv_bfloat16 g_x1[(size_t)MROWS * DIM];
__device__ __nv_bfloat16 g_h0[(size_t)MROWS * DIM];
__device__ __nv_bfloat16 g_h1[(size_t)MROWS * DIM];
__device__ __nv_bfloat16 g_u0[DIM * DIM];
__device__ __nv_bfloat16 g_u1[DIM * DIM];
__device__ __nv_bfloat16 g_w20[DIM * DIM];
__device__ __nv_bfloat16 g_w21[DIM * DIM];
__device__ float         g_w2part[4][DIM * DIM];

// ---- helpers ----
__device__ __forceinline__ uint32_t smem_u32(const void* p) {
    uint32_t a;
    asm("{ .reg .u64 t; cvta.to.shared.u64 t, %1; cvt.u32.u64 %0, t; }"
        : "=r"(a) : "l"(p));
    return a;
}
__device__ __forceinline__ void cp16(uint32_t dst, const void* src) {
    asm volatile("cp.async.cg.shared.global [%0], [%1], 16;" :: "r"(dst), "l"(src));
}
__device__ __forceinline__ void ldsm4(uint32_t* r, uint32_t addr) {
    asm volatile("ldmatrix.sync.aligned.m8n8.x4.shared.b16 {%0,%1,%2,%3}, [%4];"
                 : "=r"(r[0]), "=r"(r[1]), "=r"(r[2]), "=r"(r[3]) : "r"(addr));
}
__device__ __forceinline__ void mma16816(float* d, const uint32_t* a,
                                         uint32_t b0, uint32_t b1) {
    asm volatile(
        "mma.sync.aligned.m16n8k16.row.col.f32.bf16.bf16.f32 "
        "{%0,%1,%2,%3}, {%4,%5,%6,%7}, {%8,%9}, {%0,%1,%2,%3};"
        : "+f"(d[0]), "+f"(d[1]), "+f"(d[2]), "+f"(d[3])
        : "r"(a[0]), "r"(a[1]), "r"(a[2]), "r"(a[3]), "r"(b0), "r"(b1));
}
__device__ __forceinline__ void split_bf16(float v, __nv_bfloat16& hi, __nv_bfloat16& lo) {
    hi = __float2bfloat16_rn(v);
    lo = __float2bfloat16_rn(v - __bfloat162float(hi));
}

// ============================================================================
// Tensor-core NT GEMM: C[M,N] = (A0+A1) @ (B0+B1)^T, all K-contiguous.
// CTA 128x128, BK=32, 256 thr (8 warps, 2m x 4n, warp tile 64x32),
// 2-stage cp.async pipeline. Inner loop is PRODUCT-MAJOR: each accumulator
// is touched once per 16-instruction pass -> no HMMA dependency stalls.
// MODE 0: threshold |v|>1e-3, re-split to bf16 H0/H1.  MODE 1: +bias, fp32.
// ============================================================================
#define NCHUNK 24            // 768 / 32
#define BKB    64            // bytes of K per chunk-row (32 bf16)
#define ROWB   80            // padded row stride in bytes
#define MATB   (128 * ROWB)  // 10240 per operand tile
#define STAGEB (4 * MATB)    // 40960
#define NSTAGE 2
#define GEMM_SMEM (NSTAGE * STAGEB)   // 81920 -> 2 CTAs/SM

template <int MODE>
__global__ void __launch_bounds__(256, 2)
gemm_mma(const __nv_bfloat16* __restrict__ A0, const __nv_bfloat16* __restrict__ A1,
         const __nv_bfloat16* __restrict__ B0, const __nv_bfloat16* __restrict__ B1,
         float* __restrict__ outF,
         __nv_bfloat16* __restrict__ H0, __nv_bfloat16* __restrict__ H1,
         const float* __restrict__ bias)
{
    extern __shared__ char smem[];
    const uint32_t sb = smem_u32(smem);

    const int tid  = threadIdx.x;
    const int lane = tid & 31;
    const int wid  = tid >> 5;
    const int wm   = wid >> 2;
    const int wn   = wid & 3;
    const int bm   = blockIdx.y * 128;
    const int bn   = blockIdx.x * 128;

    const int lrow = tid >> 1;
    const int lqB  = (tid & 1) * 32;
    const char* gA0 = (const char*)(A0 + (size_t)(bm + lrow) * DIM) + lqB;
    const char* gA1 = (const char*)(A1 + (size_t)(bm + lrow) * DIM) + lqB;
    const char* gB0 = (const char*)(B0 + (size_t)(bn + lrow) * DIM) + lqB;
    const char* gB1 = (const char*)(B1 + (size_t)(bn + lrow) * DIM) + lqB;
    const uint32_t sdst = lrow * ROWB + lqB;

#define LOAD_CHUNK(c) do { \
    const uint32_t _st = sb + ((c) % NSTAGE) * STAGEB + sdst; \
    const int _kb = (c) * BKB; \
    cp16(_st,                gA0 + _kb); cp16(_st + 16,            gA0 + _kb + 16); \
    cp16(_st + MATB,         gA1 + _kb); cp16(_st + MATB + 16,     gA1 + _kb + 16); \
    cp16(_st + 2 * MATB,     gB0 + _kb); cp16(_st + 2 * MATB + 16, gB0 + _kb + 16); \
    cp16(_st + 3 * MATB,     gB1 + _kb); cp16(_st + 3 * MATB + 16, gB1 + _kb + 16); \
    asm volatile("cp.async.commit_group;" ::: "memory"); \
} while (0)

    const int lr8 = ((lane >> 3) & 1) * 8 + (lane & 7);
    const int lcb = ((lane >> 4) & 1) * 16;
    const uint32_t aRow = wm * 64 + lr8;
    const uint32_t bRow = wn * 32 + lr8;

    float acc[4][4][4];
#pragma unroll
    for (int i = 0; i < 4; i++)
#pragma unroll
        for (int j = 0; j < 4; j++)
#pragma unroll
            for (int k = 0; k < 4; k++) acc[i][j][k] = 0.0f;

    LOAD_CHUNK(0);
    LOAD_CHUNK(1);

    for (int c = 0; c < NCHUNK; c++) {
        if (c + 1 < NCHUNK) asm volatile("cp.async.wait_group 1;" ::: "memory");
        else                asm volatile("cp.async.wait_group 0;" ::: "memory");
        __syncthreads();

        const uint32_t stg = sb + (c % NSTAGE) * STAGEB;
#pragma unroll
        for (int ks = 0; ks < 2; ks++) {
            // Fragments needed by pass 0 first; af1/bf1 loads overlap pass 0.
            uint32_t af0[4][4], af1[4][4], bf0[2][4], bf1[2][4];
#pragma unroll
            for (int mt = 0; mt < 4; mt++)
                ldsm4(af0[mt], stg + (aRow + mt * 16) * ROWB + ks * 32 + lcb);
#pragma unroll
            for (int ng = 0; ng < 2; ng++)
                ldsm4(bf0[ng], stg + 2 * MATB + (bRow + ng * 16) * ROWB + ks * 32 + lcb);
#pragma unroll
            for (int ng = 0; ng < 2; ng++)
                ldsm4(bf1[ng], stg + 3 * MATB + (bRow + ng * 16) * ROWB + ks * 32 + lcb);
#pragma unroll
            for (int mt = 0; mt < 4; mt++)
                ldsm4(af1[mt], stg + MATB + (aRow + mt * 16) * ROWB + ks * 32 + lcb);

            // Pass 0: A0*B0 — 16 independent MMAs
#pragma unroll
            for (int mt = 0; mt < 4; mt++)
#pragma unroll
                for (int nt = 0; nt < 4; nt++) {
                    const int ng = nt >> 1, p = nt & 1;
                    mma16816(acc[mt][nt], af0[mt], bf0[ng][p], bf0[ng][p + 2]);
                }
            // Pass 1: A0*B1
#pragma unroll
            for (int mt = 0; mt < 4; mt++)
#pragma unroll
                for (int nt = 0; nt < 4; nt++) {
                    const int ng = nt >> 1, p = nt & 1;
                    mma16816(acc[mt][nt], af0[mt], bf1[ng][p], bf1[ng][p + 2]);
                }
            // Pass 2: A1*B0
#pragma unroll
            for (int mt = 0; mt < 4; mt++)
#pragma unroll
                for (int nt = 0; nt < 4; nt++) {
                    const int ng = nt >> 1, p = nt & 1;
                    mma16816(acc[mt][nt], af1[mt], bf0[ng][p], bf0[ng][p + 2]);
                }
        }

        if (c + 2 < NCHUNK) {
            __syncthreads();
            LOAD_CHUNK(c + 2);
        }
    }

    // ---- epilogue ----
    const int r0 = bm + wm * 64 + (lane >> 2);
    const int c0 = bn + wn * 32 + (lane & 3) * 2;
#pragma unroll
    for (int mt = 0; mt < 4; mt++) {
#pragma unroll
        for (int nt = 0; nt < 4; nt++) {
            const int col = c0 + nt * 8;
#pragma unroll
            for (int half = 0; half < 2; half++) {
                const int row = r0 + mt * 16 + half * 8;
                float vx = acc[mt][nt][half * 2];
                float vy = acc[mt][nt][half * 2 + 1];
                if (MODE == 0) {
                    vx = (fabsf(vx) > 1e-3f) ? vx : 0.0f;
                    vy = (fabsf(vy) > 1e-3f) ? vy : 0.0f;
                    __nv_bfloat162 hi, lo;
                    split_bf16(vx, hi.x, lo.x);
                    split_bf16(vy, hi.y, lo.y);
                    const size_t idx = (size_t)row * DIM + col;
                    *(__nv_bfloat162*)(H0 + idx) = hi;
                    *(__nv_bfloat162*)(H1 + idx) = lo;
                } else {
                    const float2 bb = *(const float2*)&bias[col];
                    float2 v = make_float2(vx + bb.x, vy + bb.y);
                    *(float2*)(outF + (size_t)row * DIM + col) = v;
                }
            }
        }
    }
}

// ============================================================================
// Elementwise fp32 -> (bf16 hi, bf16 lo) split.
// ============================================================================
__global__ void split_kernel(const float4* __restrict__ src,
                             __nv_bfloat16* __restrict__ d0,
                             __nv_bfloat16* __restrict__ d1, int n4)
{
    int i = blockIdx.x * blockDim.x + threadIdx.x;
    if (i >= n4) return;
    float4 v = src[i];
    __nv_bfloat162 h0, h1, l0, l1;
    split_bf16(v.x, h0.x, l0.x);
    split_bf16(v.y, h0.y, l0.y);
    split_bf16(v.z, h1.x, l1.x);
    split_bf16(v.w, h1.y, l1.y);
    __nv_bfloat162* p0 = (__nv_bfloat162*)(d0 + (size_t)i * 4);
    __nv_bfloat162* p1 = (__nv_bfloat162*)(d1 + (size_t)i * 4);
    p0[0] = h0; p0[1] = h1;
    p1[0] = l0; p1[1] = l1;
}

// ============================================================================
// W2 prep, split-K: partial[z] = VT[:, zK..] @ weight[zK.., :] over K/4=192.
// Then reduce+split kernel sums 4 partials -> bf16 hi/lo. Deterministic.
// ============================================================================
__global__ void __launch_bounds__(256)
gemm_nn_part(const float* __restrict__ A, const float* __restrict__ B,
             float* __restrict__ Cpart, int N, int K)
{
    constexpr int BK = 16;
    __shared__ float As[BK][68];
    __shared__ float Bs[BK][64];

    const int bp = blockIdx.y * 64;
    const int bc = blockIdx.x * 64;
    const int kz = blockIdx.z;           // 0..3
    const int kbeg = kz * (K / 4);
    const int kend = kbeg + (K / 4);
    float* C = Cpart + (size_t)kz * N * N;

    const int t  = threadIdx.x;
    const int tx = t & 15;
    const int ty = t >> 4;

    float acc[4][4] = {};

    for (int k0 = kbeg; k0 < kend; k0 += BK) {
        {
            const int r = t >> 2;
            const int o4 = (t & 3) * 4;
            float4 av = *(const float4*)(A + (size_t)(bp + r) * K + k0 + o4);
            As[o4 + 0][r] = av.x; As[o4 + 1][r] = av.y;
            As[o4 + 2][r] = av.z; As[o4 + 3][r] = av.w;
        }
        {
            const int o  = t >> 4;
            const int c4 = (t & 15) * 4;
            *(float4*)&Bs[o][c4] = *(const float4*)(B + (size_t)(k0 + o) * N + bc + c4);
        }
        __syncthreads();
#pragma unroll
        for (int o = 0; o < BK; o++) {
            float a[4], b[4];
#pragma unroll
            for (int i = 0; i < 4; i++) a[i] = As[o][ty * 4 + i];
#pragma unroll
            for (int j = 0; j < 4; j++) b[j] = Bs[o][tx * 4 + j];
#pragma unroll
            for (int i = 0; i < 4; i++)
#pragma unroll
                for (int j = 0; j < 4; j++) acc[i][j] += a[i] * b[j];
        }
        __syncthreads();
    }

#pragma unroll
    for (int i = 0; i < 4; i++)
#pragma unroll
        for (int j = 0; j < 4; j++)
            C[(size_t)(bp + ty * 4 + i) * N + bc + tx * 4 + j] = acc[i][j];
}

__global__ void reduce_split_w2(const float* __restrict__ Cpart,
                                __nv_bfloat16* __restrict__ C0,
                                __nv_bfloat16* __restrict__ C1, int n)
{
    int i = blockIdx.x * blockDim.x + threadIdx.x;
    if (i >= n) return;
    float v = Cpart[i] + Cpart[i + n] + Cpart[i + 2 * n] + Cpart[i + 3 * n];
    __nv_bfloat16 hi, lo;
    split_bf16(v, hi, lo);
    C0[i] = hi;
    C1[i] = lo;
}

// ============================================================================
// kernel_launch — inputs: x, weight, bias, U, VT; output fp32 [32768,768]
// ============================================================================
extern "C" void kernel_launch(void* const* d_in, const int* in_sizes, int n_in,
                              void* d_out, int out_size)
{
    const float* x      = (const float*)d_in[0];
    const float* weight = (const float*)d_in[1];
    const float* bias   = (const float*)d_in[2];
    const float* U      = (const float*)d_in[3];
    const float* VT     = (const float*)d_in[4];
    float* out          = (float*)d_out;

    __nv_bfloat16 *x0, *x1, *h0, *h1, *u0, *u1, *w20, *w21;
    float* w2p;
    cudaGetSymbolAddress((void**)&x0,  g_x0);
    cudaGetSymbolAddress((void**)&x1,  g_x1);
    cudaGetSymbolAddress((void**)&h0,  g_h0);
    cudaGetSymbolAddress((void**)&h1,  g_h1);
    cudaGetSymbolAddress((void**)&u0,  g_u0);
    cudaGetSymbolAddress((void**)&u1,  g_u1);
    cudaGetSymbolAddress((void**)&w20, g_w20);
    cudaGetSymbolAddress((void**)&w21, g_w21);
    cudaGetSymbolAddress((void**)&w2p, g_w2part);

    cudaFuncSetAttribute(gemm_mma<0>, cudaFuncAttributeMaxDynamicSharedMemorySize, GEMM_SMEM);
    cudaFuncSetAttribute(gemm_mma<1>, cudaFuncAttributeMaxDynamicSharedMemorySize, GEMM_SMEM);

    const int M = in_sizes[0] / DIM;   // 32768

    {
        int n4 = M * DIM / 4;
        split_kernel<<<(n4 + 255) / 256, 256>>>((const float4*)x, x0, x1, n4);
    }
    {
        int n4 = DIM * DIM / 4;
        split_kernel<<<(n4 + 255) / 256, 256>>>((const float4*)U, u0, u1, n4);
    }
    // W2 = VT @ weight via split-K partials, then reduce+split to bf16 pair.
    gemm_nn_part<<<dim3(DIM / 64, DIM / 64, 4), 256>>>(VT, weight, w2p, DIM, DIM);
    {
        int n = DIM * DIM;
        reduce_split_w2<<<(n + 255) / 256, 256>>>(w2p, w20, w21, n);
    }

    // GEMM1: h = threshold(x @ U^T) -> h0,h1
    gemm_mma<0><<<dim3(DIM / 128, M / 128), 256, GEMM_SMEM>>>(
        x0, x1, u0, u1, nullptr, h0, h1, nullptr);
    // GEMM2: out = h @ W2^T + bias
    gemm_mma<1><<<dim3(DIM / 128, M / 128), 256, GEMM_SMEM>>>(
        h0, h1, w20, w21, out, nullptr, nullptr, bias);
}

// round 7
// speedup vs baseline: 3.1291x; 1.4300x over previous
#include <cuda_runtime.h>
#include <cuda_fp16.h>
#include <stdint.h>

// ============================================================================
// SparseGradLinear via base-ISA tensor cores (ldmatrix + mma.sync fp16):
//   h   = threshold(x @ U^T)           [32768, 768]
//   out = h @ (VT @ weight)^T + bias   [32768, 768]
// R7: fp16 2-product split precision. B = B0+B1 (fp16 hi/lo, 22-bit mantissa);
// A single fp16. C = A0B0 + A0B1 = A0*B exactly; dropped (A-A0)*B ~ 2^-12.
// 33% less tensor work than the bf16 3-product scheme (legacy HMMA-bound).
// ============================================================================

#define DIM    768
#define MROWS  32768

__device__ __half g_x0[(size_t)MROWS * DIM];
__device__ __half g_h0[(size_t)MROWS * DIM];
__device__ __half g_u0[DIM * DIM];
__device__ __half g_u1[DIM * DIM];
__device__ __half g_w20[DIM * DIM];
__device__ __half g_w21[DIM * DIM];
__device__ float  g_w2part[4][DIM * DIM];

// ---- helpers ----
__device__ __forceinline__ uint32_t smem_u32(const void* p) {
    uint32_t a;
    asm("{ .reg .u64 t; cvta.to.shared.u64 t, %1; cvt.u32.u64 %0, t; }"
        : "=r"(a) : "l"(p));
    return a;
}
__device__ __forceinline__ void cp16(uint32_t dst, const void* src) {
    asm volatile("cp.async.cg.shared.global [%0], [%1], 16;" :: "r"(dst), "l"(src));
}
__device__ __forceinline__ void ldsm4(uint32_t* r, uint32_t addr) {
    asm volatile("ldmatrix.sync.aligned.m8n8.x4.shared.b16 {%0,%1,%2,%3}, [%4];"
                 : "=r"(r[0]), "=r"(r[1]), "=r"(r[2]), "=r"(r[3]) : "r"(addr));
}
__device__ __forceinline__ void mma16816(float* d, const uint32_t* a,
                                         uint32_t b0, uint32_t b1) {
    asm volatile(
        "mma.sync.aligned.m16n8k16.row.col.f32.f16.f16.f32 "
        "{%0,%1,%2,%3}, {%4,%5,%6,%7}, {%8,%9}, {%0,%1,%2,%3};"
        : "+f"(d[0]), "+f"(d[1]), "+f"(d[2]), "+f"(d[3])
        : "r"(a[0]), "r"(a[1]), "r"(a[2]), "r"(a[3]), "r"(b0), "r"(b1));
}
__device__ __forceinline__ void split_fp16(float v, __half& hi, __half& lo) {
    hi = __float2half_rn(v);
    lo = __float2half_rn(v - __half2float(hi));
}

// ============================================================================
// Tensor-core NT GEMM: C[M,N] = A0[M,K] @ (B0+B1)[N,K]^T, all K-contiguous.
// CTA 128x128, BK=32, 256 thr (8 warps, 2m x 4n, warp tile 64x32),
// 2-stage cp.async pipeline; 3 operand tiles per stage (A,B0,B1), 80B rows.
// MODE 0: threshold |v|>1e-3, write fp16 H.   MODE 1: +bias, fp32 out.
// ============================================================================
#define NCHUNK 24            // 768 / 32
#define BKB    64            // bytes of K per chunk-row (32 fp16)
#define ROWB   80            // padded row stride in bytes
#define MATB   (128 * ROWB)  // 10240 per operand tile
#define STAGEB (3 * MATB)    // 30720
#define NSTAGE 2
#define GEMM_SMEM (NSTAGE * STAGEB)   // 61440

template <int MODE>
__global__ void __launch_bounds__(256, 2)
gemm_mma(const __half* __restrict__ A0,
         const __half* __restrict__ B0, const __half* __restrict__ B1,
         float* __restrict__ outF, __half* __restrict__ H,
         const float* __restrict__ bias)
{
    extern __shared__ char smem[];
    const uint32_t sb = smem_u32(smem);

    const int tid  = threadIdx.x;
    const int lane = tid & 31;
    const int wid  = tid >> 5;
    const int wm   = wid >> 2;
    const int wn   = wid & 3;
    const int bm   = blockIdx.y * 128;
    const int bn   = blockIdx.x * 128;

    const int lrow = tid >> 1;
    const int lqB  = (tid & 1) * 32;
    const char* gA0 = (const char*)(A0 + (size_t)(bm + lrow) * DIM) + lqB;
    const char* gB0 = (const char*)(B0 + (size_t)(bn + lrow) * DIM) + lqB;
    const char* gB1 = (const char*)(B1 + (size_t)(bn + lrow) * DIM) + lqB;
    const uint32_t sdst = lrow * ROWB + lqB;

#define LOAD_CHUNK(c) do { \
    const uint32_t _st = sb + ((c) % NSTAGE) * STAGEB + sdst; \
    const int _kb = (c) * BKB; \
    cp16(_st,                gA0 + _kb); cp16(_st + 16,            gA0 + _kb + 16); \
    cp16(_st + MATB,         gB0 + _kb); cp16(_st + MATB + 16,     gB0 + _kb + 16); \
    cp16(_st + 2 * MATB,     gB1 + _kb); cp16(_st + 2 * MATB + 16, gB1 + _kb + 16); \
    asm volatile("cp.async.commit_group;" ::: "memory"); \
} while (0)

    const int lr8 = ((lane >> 3) & 1) * 8 + (lane & 7);
    const int lcb = ((lane >> 4) & 1) * 16;
    const uint32_t aRow = wm * 64 + lr8;
    const uint32_t bRow = wn * 32 + lr8;

    float acc[4][4][4];
#pragma unroll
    for (int i = 0; i < 4; i++)
#pragma unroll
        for (int j = 0; j < 4; j++)
#pragma unroll
            for (int k = 0; k < 4; k++) acc[i][j][k] = 0.0f;

    LOAD_CHUNK(0);
    LOAD_CHUNK(1);

    for (int c = 0; c < NCHUNK; c++) {
        if (c + 1 < NCHUNK) asm volatile("cp.async.wait_group 1;" ::: "memory");
        else                asm volatile("cp.async.wait_group 0;" ::: "memory");
        __syncthreads();

        const uint32_t stg = sb + (c % NSTAGE) * STAGEB;
#pragma unroll
        for (int ks = 0; ks < 2; ks++) {
            uint32_t af[4][4], bf0[2][4], bf1[2][4];
#pragma unroll
            for (int mt = 0; mt < 4; mt++)
                ldsm4(af[mt], stg + (aRow + mt * 16) * ROWB + ks * 32 + lcb);
#pragma unroll
            for (int ng = 0; ng < 2; ng++)
                ldsm4(bf0[ng], stg + MATB + (bRow + ng * 16) * ROWB + ks * 32 + lcb);
#pragma unroll
            for (int ng = 0; ng < 2; ng++)
                ldsm4(bf1[ng], stg + 2 * MATB + (bRow + ng * 16) * ROWB + ks * 32 + lcb);

            // Pass 0: A0*B0 — 16 independent MMAs
#pragma unroll
            for (int mt = 0; mt < 4; mt++)
#pragma unroll
                for (int nt = 0; nt < 4; nt++) {
                    const int ng = nt >> 1, p = nt & 1;
                    mma16816(acc[mt][nt], af[mt], bf0[ng][p], bf0[ng][p + 2]);
                }
            // Pass 1: A0*B1
#pragma unroll
            for (int mt = 0; mt < 4; mt++)
#pragma unroll
                for (int nt = 0; nt < 4; nt++) {
                    const int ng = nt >> 1, p = nt & 1;
                    mma16816(acc[mt][nt], af[mt], bf1[ng][p], bf1[ng][p + 2]);
                }
        }

        if (c + 2 < NCHUNK) {
            __syncthreads();
            LOAD_CHUNK(c + 2);
        }
    }

    // ---- epilogue ----
    const int r0 = bm + wm * 64 + (lane >> 2);
    const int c0 = bn + wn * 32 + (lane & 3) * 2;
#pragma unroll
    for (int mt = 0; mt < 4; mt++) {
#pragma unroll
        for (int nt = 0; nt < 4; nt++) {
            const int col = c0 + nt * 8;
#pragma unroll
            for (int half = 0; half < 2; half++) {
                const int row = r0 + mt * 16 + half * 8;
                float vx = acc[mt][nt][half * 2];
                float vy = acc[mt][nt][half * 2 + 1];
                if (MODE == 0) {
                    vx = (fabsf(vx) > 1e-3f) ? vx : 0.0f;
                    vy = (fabsf(vy) > 1e-3f) ? vy : 0.0f;
                    __half2 hv;
                    hv.x = __float2half_rn(vx);
                    hv.y = __float2half_rn(vy);
                    *(__half2*)(H + (size_t)row * DIM + col) = hv;
                } else {
                    const float2 bb = *(const float2*)&bias[col];
                    float2 v = make_float2(vx + bb.x, vy + bb.y);
                    *(float2*)(outF + (size_t)row * DIM + col) = v;
                }
            }
        }
    }
}

// ============================================================================
// Elementwise fp32 -> fp16 convert (single term), float4-vectorized.
// ============================================================================
__global__ void convert_fp16(const float4* __restrict__ src,
                             __half* __restrict__ dst, int n4)
{
    int i = blockIdx.x * blockDim.x + threadIdx.x;
    if (i >= n4) return;
    float4 v = src[i];
    __half2 a, b;
    a.x = __float2half_rn(v.x); a.y = __float2half_rn(v.y);
    b.x = __float2half_rn(v.z); b.y = __float2half_rn(v.w);
    __half2* p = (__half2*)(dst + (size_t)i * 4);
    p[0] = a; p[1] = b;
}

// ============================================================================
// Elementwise fp32 -> (fp16 hi, fp16 lo) split.
// ============================================================================
__global__ void split_kernel(const float4* __restrict__ src,
                             __half* __restrict__ d0,
                             __half* __restrict__ d1, int n4)
{
    int i = blockIdx.x * blockDim.x + threadIdx.x;
    if (i >= n4) return;
    float4 v = src[i];
    __half2 h0, h1, l0, l1;
    split_fp16(v.x, h0.x, l0.x);
    split_fp16(v.y, h0.y, l0.y);
    split_fp16(v.z, h1.x, l1.x);
    split_fp16(v.w, h1.y, l1.y);
    __half2* p0 = (__half2*)(d0 + (size_t)i * 4);
    __half2* p1 = (__half2*)(d1 + (size_t)i * 4);
    p0[0] = h0; p0[1] = h1;
    p1[0] = l0; p1[1] = l1;
}

// ============================================================================
// W2 prep, split-K: partial[z] = VT[:, zK..] @ weight[zK.., :] over K/4=192.
// Then reduce+split sums 4 partials -> fp16 hi/lo. Deterministic.
// ============================================================================
__global__ void __launch_bounds__(256)
gemm_nn_part(const float* __restrict__ A, const float* __restrict__ B,
             float* __restrict__ Cpart, int N, int K)
{
    constexpr int BK = 16;
    __shared__ float As[BK][68];
    __shared__ float Bs[BK][64];

    const int bp = blockIdx.y * 64;
    const int bc = blockIdx.x * 64;
    const int kz = blockIdx.z;
    const int kbeg = kz * (K / 4);
    const int kend = kbeg + (K / 4);
    float* C = Cpart + (size_t)kz * N * N;

    const int t  = threadIdx.x;
    const int tx = t & 15;
    const int ty = t >> 4;

    float acc[4][4] = {};

    for (int k0 = kbeg; k0 < kend; k0 += BK) {
        {
            const int r = t >> 2;
            const int o4 = (t & 3) * 4;
            float4 av = *(const float4*)(A + (size_t)(bp + r) * K + k0 + o4);
            As[o4 + 0][r] = av.x; As[o4 + 1][r] = av.y;
            As[o4 + 2][r] = av.z; As[o4 + 3][r] = av.w;
        }
        {
            const int o  = t >> 4;
            const int c4 = (t & 15) * 4;
            *(float4*)&Bs[o][c4] = *(const float4*)(B + (size_t)(k0 + o) * N + bc + c4);
        }
        __syncthreads();
#pragma unroll
        for (int o = 0; o < BK; o++) {
            float a[4], b[4];
#pragma unroll
            for (int i = 0; i < 4; i++) a[i] = As[o][ty * 4 + i];
#pragma unroll
            for (int j = 0; j < 4; j++) b[j] = Bs[o][tx * 4 + j];
#pragma unroll
            for (int i = 0; i < 4; i++)
#pragma unroll
                for (int j = 0; j < 4; j++) acc[i][j] += a[i] * b[j];
        }
        __syncthreads();
    }

#pragma unroll
    for (int i = 0; i < 4; i++)
#pragma unroll
        for (int j = 0; j < 4; j++)
            C[(size_t)(bp + ty * 4 + i) * N + bc + tx * 4 + j] = acc[i][j];
}

__global__ void reduce_split_w2(const float* __restrict__ Cpart,
                                __half* __restrict__ C0,
                                __half* __restrict__ C1, int n)
{
    int i = blockIdx.x * blockDim.x + threadIdx.x;
    if (i >= n) return;
    float v = Cpart[i] + Cpart[i + n] + Cpart[i + 2 * n] + Cpart[i + 3 * n];
    __half hi, lo;
    split_fp16(v, hi, lo);
    C0[i] = hi;
    C1[i] = lo;
}

// ============================================================================
// kernel_launch — inputs: x, weight, bias, U, VT; output fp32 [32768,768]
// ============================================================================
extern "C" void kernel_launch(void* const* d_in, const int* in_sizes, int n_in,
                              void* d_out, int out_size)
{
    const float* x      = (const float*)d_in[0];
    const float* weight = (const float*)d_in[1];
    const float* bias   = (const float*)d_in[2];
    const float* U      = (const float*)d_in[3];
    const float* VT     = (const float*)d_in[4];
    float* out          = (float*)d_out;

    __half *x0, *h0, *u0, *u1, *w20, *w21;
    float* w2p;
    cudaGetSymbolAddress((void**)&x0,  g_x0);
    cudaGetSymbolAddress((void**)&h0,  g_h0);
    cudaGetSymbolAddress((void**)&u0,  g_u0);
    cudaGetSymbolAddress((void**)&u1,  g_u1);
    cudaGetSymbolAddress((void**)&w20, g_w20);
    cudaGetSymbolAddress((void**)&w21, g_w21);
    cudaGetSymbolAddress((void**)&w2p, g_w2part);

    cudaFuncSetAttribute(gemm_mma<0>, cudaFuncAttributeMaxDynamicSharedMemorySize, GEMM_SMEM);
    cudaFuncSetAttribute(gemm_mma<1>, cudaFuncAttributeMaxDynamicSharedMemorySize, GEMM_SMEM);

    const int M = in_sizes[0] / DIM;   // 32768

    {
        int n4 = M * DIM / 4;
        convert_fp16<<<(n4 + 255) / 256, 256>>>((const float4*)x, x0, n4);
    }
    {
        int n4 = DIM * DIM / 4;
        split_kernel<<<(n4 + 255) / 256, 256>>>((const float4*)U, u0, u1, n4);
    }
    // W2 = VT @ weight via split-K partials, then reduce+split to fp16 pair.
    gemm_nn_part<<<dim3(DIM / 64, DIM / 64, 4), 256>>>(VT, weight, w2p, DIM, DIM);
    {
        int n = DIM * DIM;
        reduce_split_w2<<<(n + 255) / 256, 256>>>(w2p, w20, w21, n);
    }

    // GEMM1: h = threshold(x0 @ (u0+u1)^T) -> fp16 h0
    gemm_mma<0><<<dim3(DIM / 128, M / 128), 256, GEMM_SMEM>>>(
        x0, u0, u1, nullptr, h0, nullptr);
    // GEMM2: out = h0 @ (w20+w21)^T + bias
    gemm_mma<1><<<dim3(DIM / 128, M / 128), 256, GEMM_SMEM>>>(
        h0, w20, w21, out, nullptr, bias);
}

// round 8
// speedup vs baseline: 3.8055x; 1.2161x over previous
#include <cuda_runtime.h>
#include <cuda_fp16.h>
#include <stdint.h>

// ============================================================================
// SparseGradLinear via base-ISA tensor cores (ldmatrix + mma.sync fp16):
//   h   = threshold(x @ U^T)           [32768, 768]
//   out = h @ (VT @ weight)^T + bias   [32768, 768]
// R8: GEMM1 = 2-product split (A=fp16(x); B=U as fp16 hi+lo).
//     GEMM2 = 1-product (h exact fp16, W2 single fp16) — halves GEMM2 work.
// Error model: GEMM1 dropped term ~2^-12, GEMM2 W2 rounding ~2^-11/sqrt(3)
// -> total ~5.7e-4 vs 1e-3 gate.
// ============================================================================

#define DIM    768
#define MROWS  32768

__device__ __half g_x0[(size_t)MROWS * DIM];
__device__ __half g_h0[(size_t)MROWS * DIM];
__device__ __half g_u0[DIM * DIM];
__device__ __half g_u1[DIM * DIM];
__device__ __half g_w20[DIM * DIM];
__device__ float  g_w2part[4][DIM * DIM];

// ---- helpers ----
__device__ __forceinline__ uint32_t smem_u32(const void* p) {
    uint32_t a;
    asm("{ .reg .u64 t; cvta.to.shared.u64 t, %1; cvt.u32.u64 %0, t; }"
        : "=r"(a) : "l"(p));
    return a;
}
__device__ __forceinline__ void cp16(uint32_t dst, const void* src) {
    asm volatile("cp.async.cg.shared.global [%0], [%1], 16;" :: "r"(dst), "l"(src));
}
__device__ __forceinline__ void ldsm4(uint32_t* r, uint32_t addr) {
    asm volatile("ldmatrix.sync.aligned.m8n8.x4.shared.b16 {%0,%1,%2,%3}, [%4];"
                 : "=r"(r[0]), "=r"(r[1]), "=r"(r[2]), "=r"(r[3]) : "r"(addr));
}
__device__ __forceinline__ void mma16816(float* d, const uint32_t* a,
                                         uint32_t b0, uint32_t b1) {
    asm volatile(
        "mma.sync.aligned.m16n8k16.row.col.f32.f16.f16.f32 "
        "{%0,%1,%2,%3}, {%4,%5,%6,%7}, {%8,%9}, {%0,%1,%2,%3};"
        : "+f"(d[0]), "+f"(d[1]), "+f"(d[2]), "+f"(d[3])
        : "r"(a[0]), "r"(a[1]), "r"(a[2]), "r"(a[3]), "r"(b0), "r"(b1));
}
__device__ __forceinline__ void split_fp16(float v, __half& hi, __half& lo) {
    hi = __float2half_rn(v);
    lo = __float2half_rn(v - __half2float(hi));
}

// ============================================================================
// Tensor-core NT GEMM. MODE 0 (GEMM1): C = A0 @ (B0+B1)^T, threshold, fp16 H.
//                      MODE 1 (GEMM2): C = A0 @ B0^T + bias, fp32 out.
// CTA 128x128, BK=32, 256 thr (8 warps, 2m x 4n, warp tile 64x32),
// 2-stage cp.async pipeline, 80B padded rows.
// ============================================================================
#define NCHUNK 24            // 768 / 32
#define BKB    64            // bytes of K per chunk-row (32 fp16)
#define ROWB   80            // padded row stride in bytes
#define MATB   (128 * ROWB)  // 10240 per operand tile
#define NSTAGE 2

template <int MODE>
__global__ void __launch_bounds__(256, 2)
gemm_mma(const __half* __restrict__ A0,
         const __half* __restrict__ B0, const __half* __restrict__ B1,
         float* __restrict__ outF, __half* __restrict__ H,
         const float* __restrict__ bias)
{
    constexpr int NTILE = (MODE == 0) ? 3 : 2;   // A,B0[,B1]
    constexpr int STB   = NTILE * MATB;

    extern __shared__ char smem[];
    const uint32_t sb = smem_u32(smem);

    const int tid  = threadIdx.x;
    const int lane = tid & 31;
    const int wid  = tid >> 5;
    const int wm   = wid >> 2;
    const int wn   = wid & 3;
    const int bm   = blockIdx.y * 128;
    const int bn   = blockIdx.x * 128;

    const int lrow = tid >> 1;
    const int lqB  = (tid & 1) * 32;
    const char* gA0 = (const char*)(A0 + (size_t)(bm + lrow) * DIM) + lqB;
    const char* gB0 = (const char*)(B0 + (size_t)(bn + lrow) * DIM) + lqB;
    const char* gB1 = (MODE == 0)
        ? (const char*)(B1 + (size_t)(bn + lrow) * DIM) + lqB : nullptr;
    const uint32_t sdst = lrow * ROWB + lqB;

    auto load_chunk = [&](int c) {
        const uint32_t st = sb + (c % NSTAGE) * STB + sdst;
        const int kb = c * BKB;
        cp16(st,            gA0 + kb); cp16(st + 16,        gA0 + kb + 16);
        cp16(st + MATB,     gB0 + kb); cp16(st + MATB + 16, gB0 + kb + 16);
        if (MODE == 0) {
            cp16(st + 2 * MATB,      gB1 + kb);
            cp16(st + 2 * MATB + 16, gB1 + kb + 16);
        }
        asm volatile("cp.async.commit_group;" ::: "memory");
    };

    const int lr8 = ((lane >> 3) & 1) * 8 + (lane & 7);
    const int lcb = ((lane >> 4) & 1) * 16;
    const uint32_t aRow = wm * 64 + lr8;
    const uint32_t bRow = wn * 32 + lr8;

    float acc[4][4][4];
#pragma unroll
    for (int i = 0; i < 4; i++)
#pragma unroll
        for (int j = 0; j < 4; j++)
#pragma unroll
            for (int k = 0; k < 4; k++) acc[i][j][k] = 0.0f;

    load_chunk(0);
    load_chunk(1);

    for (int c = 0; c < NCHUNK; c++) {
        if (c + 1 < NCHUNK) asm volatile("cp.async.wait_group 1;" ::: "memory");
        else                asm volatile("cp.async.wait_group 0;" ::: "memory");
        __syncthreads();

        const uint32_t stg = sb + (c % NSTAGE) * STB;
#pragma unroll
        for (int ks = 0; ks < 2; ks++) {
            uint32_t af[4][4], bf0[2][4], bf1[2][4];
#pragma unroll
            for (int mt = 0; mt < 4; mt++)
                ldsm4(af[mt], stg + (aRow + mt * 16) * ROWB + ks * 32 + lcb);
#pragma unroll
            for (int ng = 0; ng < 2; ng++)
                ldsm4(bf0[ng], stg + MATB + (bRow + ng * 16) * ROWB + ks * 32 + lcb);
            if (MODE == 0) {
#pragma unroll
                for (int ng = 0; ng < 2; ng++)
                    ldsm4(bf1[ng], stg + 2 * MATB + (bRow + ng * 16) * ROWB + ks * 32 + lcb);
            }

            // Pass 0: A0*B0 — 16 independent MMAs
#pragma unroll
            for (int mt = 0; mt < 4; mt++)
#pragma unroll
                for (int nt = 0; nt < 4; nt++) {
                    const int ng = nt >> 1, p = nt & 1;
                    mma16816(acc[mt][nt], af[mt], bf0[ng][p], bf0[ng][p + 2]);
                }
            // Pass 1 (GEMM1 only): A0*B1
            if (MODE == 0) {
#pragma unroll
                for (int mt = 0; mt < 4; mt++)
#pragma unroll
                    for (int nt = 0; nt < 4; nt++) {
                        const int ng = nt >> 1, p = nt & 1;
                        mma16816(acc[mt][nt], af[mt], bf1[ng][p], bf1[ng][p + 2]);
                    }
            }
        }

        if (c + 2 < NCHUNK) {
            __syncthreads();
            load_chunk(c + 2);
        }
    }

    // ---- epilogue ----
    const int r0 = bm + wm * 64 + (lane >> 2);
    const int c0 = bn + wn * 32 + (lane & 3) * 2;
#pragma unroll
    for (int mt = 0; mt < 4; mt++) {
#pragma unroll
        for (int nt = 0; nt < 4; nt++) {
            const int col = c0 + nt * 8;
#pragma unroll
            for (int half = 0; half < 2; half++) {
                const int row = r0 + mt * 16 + half * 8;
                float vx = acc[mt][nt][half * 2];
                float vy = acc[mt][nt][half * 2 + 1];
                if (MODE == 0) {
                    vx = (fabsf(vx) > 1e-3f) ? vx : 0.0f;
                    vy = (fabsf(vy) > 1e-3f) ? vy : 0.0f;
                    __half2 hv;
                    hv.x = __float2half_rn(vx);
                    hv.y = __float2half_rn(vy);
                    *(__half2*)(H + (size_t)row * DIM + col) = hv;
                } else {
                    const float2 bb = *(const float2*)&bias[col];
                    float2 v = make_float2(vx + bb.x, vy + bb.y);
                    *(float2*)(outF + (size_t)row * DIM + col) = v;
                }
            }
        }
    }
}

// ============================================================================
// Elementwise fp32 -> fp16 convert (single term), float4-vectorized.
// ============================================================================
__global__ void convert_fp16(const float4* __restrict__ src,
                             __half* __restrict__ dst, int n4)
{
    int i = blockIdx.x * blockDim.x + threadIdx.x;
    if (i >= n4) return;
    float4 v = src[i];
    __half2 a, b;
    a.x = __float2half_rn(v.x); a.y = __float2half_rn(v.y);
    b.x = __float2half_rn(v.z); b.y = __float2half_rn(v.w);
    __half2* p = (__half2*)(dst + (size_t)i * 4);
    p[0] = a; p[1] = b;
}

// ============================================================================
// Elementwise fp32 -> (fp16 hi, fp16 lo) split (for U).
// ============================================================================
__global__ void split_kernel(const float4* __restrict__ src,
                             __half* __restrict__ d0,
                             __half* __restrict__ d1, int n4)
{
    int i = blockIdx.x * blockDim.x + threadIdx.x;
    if (i >= n4) return;
    float4 v = src[i];
    __half2 h0, h1, l0, l1;
    split_fp16(v.x, h0.x, l0.x);
    split_fp16(v.y, h0.y, l0.y);
    split_fp16(v.z, h1.x, l1.x);
    split_fp16(v.w, h1.y, l1.y);
    __half2* p0 = (__half2*)(d0 + (size_t)i * 4);
    __half2* p1 = (__half2*)(d1 + (size_t)i * 4);
    p0[0] = h0; p0[1] = h1;
    p1[0] = l0; p1[1] = l1;
}

// ============================================================================
// W2 prep, split-K: partial[z] = VT[:, zK..] @ weight[zK.., :] over K/4=192.
// Reduce sums 4 partials -> single fp16 (GEMM2 is 1-product). Deterministic.
// ============================================================================
__global__ void __launch_bounds__(256)
gemm_nn_part(const float* __restrict__ A, const float* __restrict__ B,
             float* __restrict__ Cpart, int N, int K)
{
    constexpr int BK = 16;
    __shared__ float As[BK][68];
    __shared__ float Bs[BK][64];

    const int bp = blockIdx.y * 64;
    const int bc = blockIdx.x * 64;
    const int kz = blockIdx.z;
    const int kbeg = kz * (K / 4);
    const int kend = kbeg + (K / 4);
    float* C = Cpart + (size_t)kz * N * N;

    const int t  = threadIdx.x;
    const int tx = t & 15;
    const int ty = t >> 4;

    float acc[4][4] = {};

    for (int k0 = kbeg; k0 < kend; k0 += BK) {
        {
            const int r = t >> 2;
            const int o4 = (t & 3) * 4;
            float4 av = *(const float4*)(A + (size_t)(bp + r) * K + k0 + o4);
            As[o4 + 0][r] = av.x; As[o4 + 1][r] = av.y;
            As[o4 + 2][r] = av.z; As[o4 + 3][r] = av.w;
        }
        {
            const int o  = t >> 4;
            const int c4 = (t & 15) * 4;
            *(float4*)&Bs[o][c4] = *(const float4*)(B + (size_t)(k0 + o) * N + bc + c4);
        }
        __syncthreads();
#pragma unroll
        for (int o = 0; o < BK; o++) {
            float a[4], b[4];
#pragma unroll
            for (int i = 0; i < 4; i++) a[i] = As[o][ty * 4 + i];
#pragma unroll
            for (int j = 0; j < 4; j++) b[j] = Bs[o][tx * 4 + j];
#pragma unroll
            for (int i = 0; i < 4; i++)
#pragma unroll
                for (int j = 0; j < 4; j++) acc[i][j] += a[i] * b[j];
        }
        __syncthreads();
    }

#pragma unroll
    for (int i = 0; i < 4; i++)
#pragma unroll
        for (int j = 0; j < 4; j++)
            C[(size_t)(bp + ty * 4 + i) * N + bc + tx * 4 + j] = acc[i][j];
}

__global__ void reduce_w2(const float* __restrict__ Cpart,
                          __half* __restrict__ C0, int n)
{
    int i = blockIdx.x * blockDim.x + threadIdx.x;
    if (i >= n) return;
    float v = Cpart[i] + Cpart[i + n] + Cpart[i + 2 * n] + Cpart[i + 3 * n];
    C0[i] = __float2half_rn(v);
}

// ============================================================================
// kernel_launch — inputs: x, weight, bias, U, VT; output fp32 [32768,768]
// ============================================================================
extern "C" void kernel_launch(void* const* d_in, const int* in_sizes, int n_in,
                              void* d_out, int out_size)
{
    const float* x      = (const float*)d_in[0];
    const float* weight = (const float*)d_in[1];
    const float* bias   = (const float*)d_in[2];
    const float* U      = (const float*)d_in[3];
    const float* VT     = (const float*)d_in[4];
    float* out          = (float*)d_out;

    __half *x0, *h0, *u0, *u1, *w20;
    float* w2p;
    cudaGetSymbolAddress((void**)&x0,  g_x0);
    cudaGetSymbolAddress((void**)&h0,  g_h0);
    cudaGetSymbolAddress((void**)&u0,  g_u0);
    cudaGetSymbolAddress((void**)&u1,  g_u1);
    cudaGetSymbolAddress((void**)&w20, g_w20);
    cudaGetSymbolAddress((void**)&w2p, g_w2part);

    const int SMEM1 = NSTAGE * 3 * MATB;   // 61440
    const int SMEM2 = NSTAGE * 2 * MATB;   // 40960
    cudaFuncSetAttribute(gemm_mma<0>, cudaFuncAttributeMaxDynamicSharedMemorySize, SMEM1);
    cudaFuncSetAttribute(gemm_mma<1>, cudaFuncAttributeMaxDynamicSharedMemorySize, SMEM2);

    const int M = in_sizes[0] / DIM;   // 32768

    {
        int n4 = M * DIM / 4;
        convert_fp16<<<(n4 + 255) / 256, 256>>>((const float4*)x, x0, n4);
    }
    {
        int n4 = DIM * DIM / 4;
        split_kernel<<<(n4 + 255) / 256, 256>>>((const float4*)U, u0, u1, n4);
    }
    // W2 = VT @ weight via split-K partials, then reduce to single fp16.
    gemm_nn_part<<<dim3(DIM / 64, DIM / 64, 4), 256>>>(VT, weight, w2p, DIM, DIM);
    {
        int n = DIM * DIM;
        reduce_w2<<<(n + 255) / 256, 256>>>(w2p, w20, n);
    }

    // GEMM1: h = threshold(x0 @ (u0+u1)^T) -> fp16 h0   (2 products)
    gemm_mma<0><<<dim3(DIM / 128, M / 128), 256, SMEM1>>>(
        x0, u0, u1, nullptr, h0, nullptr);
    // GEMM2: out = h0 @ w20^T + bias                    (1 product)
    gemm_mma<1><<<dim3(DIM / 128, M / 128), 256, SMEM2>>>(
        h0, w20, nullptr, out, nullptr, bias);
}

// round 9
// speedup vs baseline: 4.8032x; 1.2622x over previous
#include <cuda_runtime.h>
#include <cuda_fp16.h>
#include <stdint.h>

// ============================================================================
// SparseGradLinear, fully fp16 tensor-core pipeline (fp32 accumulate):
//   h   = threshold(fp16(x) @ fp16(U)^T)        [32768, 768]
//   out = fp16(h) @ fp16(VT @ weight)^T + bias  [32768, 768]
// R9: both GEMMs single-product. Error model (calibrated R7/R8):
//   x-round 2.8e-4 ⊕ U-round 2.8e-4 ⊕ h-store ⊕ W2-round 2.8e-4 ≈ 4.6e-4
//   vs 1e-3 gate. 3-stage cp.async pipeline, 2 CTAs/SM.
// ============================================================================

#define DIM    768
#define MROWS  32768

__device__ __half g_x0[(size_t)MROWS * DIM];
__device__ __half g_h0[(size_t)MROWS * DIM];
__device__ __half g_u0[DIM * DIM];
__device__ __half g_w20[DIM * DIM];
__device__ float  g_w2part[4][DIM * DIM];

// ---- helpers ----
__device__ __forceinline__ uint32_t smem_u32(const void* p) {
    uint32_t a;
    asm("{ .reg .u64 t; cvta.to.shared.u64 t, %1; cvt.u32.u64 %0, t; }"
        : "=r"(a) : "l"(p));
    return a;
}
__device__ __forceinline__ void cp16(uint32_t dst, const void* src) {
    asm volatile("cp.async.cg.shared.global [%0], [%1], 16;" :: "r"(dst), "l"(src));
}
__device__ __forceinline__ void ldsm4(uint32_t* r, uint32_t addr) {
    asm volatile("ldmatrix.sync.aligned.m8n8.x4.shared.b16 {%0,%1,%2,%3}, [%4];"
                 : "=r"(r[0]), "=r"(r[1]), "=r"(r[2]), "=r"(r[3]) : "r"(addr));
}
__device__ __forceinline__ void mma16816(float* d, const uint32_t* a,
                                         uint32_t b0, uint32_t b1) {
    asm volatile(
        "mma.sync.aligned.m16n8k16.row.col.f32.f16.f16.f32 "
        "{%0,%1,%2,%3}, {%4,%5,%6,%7}, {%8,%9}, {%0,%1,%2,%3};"
        : "+f"(d[0]), "+f"(d[1]), "+f"(d[2]), "+f"(d[3])
        : "r"(a[0]), "r"(a[1]), "r"(a[2]), "r"(a[3]), "r"(b0), "r"(b1));
}

// ============================================================================
// Tensor-core NT GEMM: C[M,N] = A[M,K] @ B[N,K]^T, single fp16 product.
// CTA 128x128, BK=32, 256 thr (8 warps, 2m x 4n, warp tile 64x32),
// 3-stage cp.async pipeline (prefetch distance 2), 80B padded rows.
// MODE 0: threshold |v|>1e-3, fp16 H out.   MODE 1: +bias, fp32 out.
// ============================================================================
#define NCHUNK 24            // 768 / 32
#define BKB    64            // bytes of K per chunk-row (32 fp16)
#define ROWB   80            // padded row stride in bytes
#define MATB   (128 * ROWB)  // 10240 per operand tile
#define NSTAGE 3
#define STB    (2 * MATB)    // A + B per stage = 20480
#define GEMM_SMEM (NSTAGE * STB)   // 61440 -> 2 CTAs/SM

template <int MODE>
__global__ void __launch_bounds__(256, 2)
gemm_mma(const __half* __restrict__ A0, const __half* __restrict__ B0,
         float* __restrict__ outF, __half* __restrict__ H,
         const float* __restrict__ bias)
{
    extern __shared__ char smem[];
    const uint32_t sb = smem_u32(smem);

    const int tid  = threadIdx.x;
    const int lane = tid & 31;
    const int wid  = tid >> 5;
    const int wm   = wid >> 2;
    const int wn   = wid & 3;
    const int bm   = blockIdx.y * 128;
    const int bn   = blockIdx.x * 128;

    const int lrow = tid >> 1;
    const int lqB  = (tid & 1) * 32;
    const char* gA0 = (const char*)(A0 + (size_t)(bm + lrow) * DIM) + lqB;
    const char* gB0 = (const char*)(B0 + (size_t)(bn + lrow) * DIM) + lqB;
    const uint32_t sdst = lrow * ROWB + lqB;

    auto load_chunk = [&](int c) {
        const uint32_t st = sb + (c % NSTAGE) * STB + sdst;
        const int kb = c * BKB;
        cp16(st,            gA0 + kb); cp16(st + 16,        gA0 + kb + 16);
        cp16(st + MATB,     gB0 + kb); cp16(st + MATB + 16, gB0 + kb + 16);
        asm volatile("cp.async.commit_group;" ::: "memory");
    };

    const int lr8 = ((lane >> 3) & 1) * 8 + (lane & 7);
    const int lcb = ((lane >> 4) & 1) * 16;
    const uint32_t aRow = wm * 64 + lr8;
    const uint32_t bRow = wn * 32 + lr8;

    float acc[4][4][4];
#pragma unroll
    for (int i = 0; i < 4; i++)
#pragma unroll
        for (int j = 0; j < 4; j++)
#pragma unroll
            for (int k = 0; k < 4; k++) acc[i][j][k] = 0.0f;

    load_chunk(0);
    load_chunk(1);
    load_chunk(2);

    for (int c = 0; c < NCHUNK; c++) {
        // Chunk c must be resident; up to (loaded - c - 1) groups may stay pending.
        const int rem = NCHUNK - 1 - c;
        if (rem >= 2)      asm volatile("cp.async.wait_group 2;" ::: "memory");
        else if (rem == 1) asm volatile("cp.async.wait_group 1;" ::: "memory");
        else               asm volatile("cp.async.wait_group 0;" ::: "memory");
        __syncthreads();   // chunk c visible; all warps done reading chunk c-NSTAGE's stage

        const uint32_t stg = sb + (c % NSTAGE) * STB;
#pragma unroll
        for (int ks = 0; ks < 2; ks++) {
            uint32_t af[4][4], bf[2][4];
#pragma unroll
            for (int mt = 0; mt < 4; mt++)
                ldsm4(af[mt], stg + (aRow + mt * 16) * ROWB + ks * 32 + lcb);
#pragma unroll
            for (int ng = 0; ng < 2; ng++)
                ldsm4(bf[ng], stg + MATB + (bRow + ng * 16) * ROWB + ks * 32 + lcb);

#pragma unroll
            for (int mt = 0; mt < 4; mt++)
#pragma unroll
                for (int nt = 0; nt < 4; nt++) {
                    const int ng = nt >> 1, p = nt & 1;
                    mma16816(acc[mt][nt], af[mt], bf[ng][p], bf[ng][p + 2]);
                }
        }

        // Reuse stage of chunk c for chunk c+NSTAGE after all warps finished it.
        if (c + NSTAGE < NCHUNK) {
            __syncthreads();
            load_chunk(c + NSTAGE);
        }
    }

    // ---- epilogue ----
    const int r0 = bm + wm * 64 + (lane >> 2);
    const int c0 = bn + wn * 32 + (lane & 3) * 2;
#pragma unroll
    for (int mt = 0; mt < 4; mt++) {
#pragma unroll
        for (int nt = 0; nt < 4; nt++) {
            const int col = c0 + nt * 8;
#pragma unroll
            for (int half = 0; half < 2; half++) {
                const int row = r0 + mt * 16 + half * 8;
                float vx = acc[mt][nt][half * 2];
                float vy = acc[mt][nt][half * 2 + 1];
                if (MODE == 0) {
                    vx = (fabsf(vx) > 1e-3f) ? vx : 0.0f;
                    vy = (fabsf(vy) > 1e-3f) ? vy : 0.0f;
                    __half2 hv;
                    hv.x = __float2half_rn(vx);
                    hv.y = __float2half_rn(vy);
                    *(__half2*)(H + (size_t)row * DIM + col) = hv;
                } else {
                    const float2 bb = *(const float2*)&bias[col];
                    float2 v = make_float2(vx + bb.x, vy + bb.y);
                    *(float2*)(outF + (size_t)row * DIM + col) = v;
                }
            }
        }
    }
}

// ============================================================================
// Elementwise fp32 -> fp16 convert, float4-vectorized.
// ============================================================================
__global__ void convert_fp16(const float4* __restrict__ src,
                             __half* __restrict__ dst, int n4)
{
    int i = blockIdx.x * blockDim.x + threadIdx.x;
    if (i >= n4) return;
    float4 v = src[i];
    __half2 a, b;
    a.x = __float2half_rn(v.x); a.y = __float2half_rn(v.y);
    b.x = __float2half_rn(v.z); b.y = __float2half_rn(v.w);
    __half2* p = (__half2*)(dst + (size_t)i * 4);
    p[0] = a; p[1] = b;
}

// ============================================================================
// W2 prep, split-K: partial[z] = VT[:, zK..] @ weight[zK.., :] over K/4=192.
// Reduce sums 4 partials -> single fp16. Deterministic (no atomics).
// ============================================================================
__global__ void __launch_bounds__(256)
gemm_nn_part(const float* __restrict__ A, const float* __restrict__ B,
             float* __restrict__ Cpart, int N, int K)
{
    constexpr int BK = 16;
    __shared__ float As[BK][68];
    __shared__ float Bs[BK][64];

    const int bp = blockIdx.y * 64;
    const int bc = blockIdx.x * 64;
    const int kz = blockIdx.z;
    const int kbeg = kz * (K / 4);
    const int kend = kbeg + (K / 4);
    float* C = Cpart + (size_t)kz * N * N;

    const int t  = threadIdx.x;
    const int tx = t & 15;
    const int ty = t >> 4;

    float acc[4][4] = {};

    for (int k0 = kbeg; k0 < kend; k0 += BK) {
        {
            const int r = t >> 2;
            const int o4 = (t & 3) * 4;
            float4 av = *(const float4*)(A + (size_t)(bp + r) * K + k0 + o4);
            As[o4 + 0][r] = av.x; As[o4 + 1][r] = av.y;
            As[o4 + 2][r] = av.z; As[o4 + 3][r] = av.w;
        }
        {
            const int o  = t >> 4;
            const int c4 = (t & 15) * 4;
            *(float4*)&Bs[o][c4] = *(const float4*)(B + (size_t)(k0 + o) * N + bc + c4);
        }
        __syncthreads();
#pragma unroll
        for (int o = 0; o < BK; o++) {
            float a[4], b[4];
#pragma unroll
            for (int i = 0; i < 4; i++) a[i] = As[o][ty * 4 + i];
#pragma unroll
            for (int j = 0; j < 4; j++) b[j] = Bs[o][tx * 4 + j];
#pragma unroll
            for (int i = 0; i < 4; i++)
#pragma unroll
                for (int j = 0; j < 4; j++) acc[i][j] += a[i] * b[j];
        }
        __syncthreads();
    }

#pragma unroll
    for (int i = 0; i < 4; i++)
#pragma unroll
        for (int j = 0; j < 4; j++)
            C[(size_t)(bp + ty * 4 + i) * N + bc + tx * 4 + j] = acc[i][j];
}

__global__ void reduce_w2(const float* __restrict__ Cpart,
                          __half* __restrict__ C0, int n)
{
    int i = blockIdx.x * blockDim.x + threadIdx.x;
    if (i >= n) return;
    float v = Cpart[i] + Cpart[i + n] + Cpart[i + 2 * n] + Cpart[i + 3 * n];
    C0[i] = __float2half_rn(v);
}

// ============================================================================
// kernel_launch — inputs: x, weight, bias, U, VT; output fp32 [32768,768]
// ============================================================================
extern "C" void kernel_launch(void* const* d_in, const int* in_sizes, int n_in,
                              void* d_out, int out_size)
{
    const float* x      = (const float*)d_in[0];
    const float* weight = (const float*)d_in[1];
    const float* bias   = (const float*)d_in[2];
    const float* U      = (const float*)d_in[3];
    const float* VT     = (const float*)d_in[4];
    float* out          = (float*)d_out;

    __half *x0, *h0, *u0, *w20;
    float* w2p;
    cudaGetSymbolAddress((void**)&x0,  g_x0);
    cudaGetSymbolAddress((void**)&h0,  g_h0);
    cudaGetSymbolAddress((void**)&u0,  g_u0);
    cudaGetSymbolAddress((void**)&w20, g_w20);
    cudaGetSymbolAddress((void**)&w2p, g_w2part);

    cudaFuncSetAttribute(gemm_mma<0>, cudaFuncAttributeMaxDynamicSharedMemorySize, GEMM_SMEM);
    cudaFuncSetAttribute(gemm_mma<1>, cudaFuncAttributeMaxDynamicSharedMemorySize, GEMM_SMEM);

    const int M = in_sizes[0] / DIM;   // 32768

    {
        int n4 = M * DIM / 4;
        convert_fp16<<<(n4 + 255) / 256, 256>>>((const float4*)x, x0, n4);
    }
    {
        int n4 = DIM * DIM / 4;
        convert_fp16<<<(n4 + 255) / 256, 256>>>((const float4*)U, u0, n4);
    }
    // W2 = VT @ weight via split-K partials, reduced to single fp16.
    gemm_nn_part<<<dim3(DIM / 64, DIM / 64, 4), 256>>>(VT, weight, w2p, DIM, DIM);
    {
        int n = DIM * DIM;
        reduce_w2<<<(n + 255) / 256, 256>>>(w2p, w20, n);
    }

    // GEMM1: h = threshold(x0 @ u0^T) -> fp16 h0
    gemm_mma<0><<<dim3(DIM / 128, M / 128), 256, GEMM_SMEM>>>(
        x0, u0, nullptr, h0, nullptr);
    // GEMM2: out = h0 @ w20^T + bias
    gemm_mma<1><<<dim3(DIM / 128, M / 128), 256, GEMM_SMEM>>>(
        h0, w20, out, nullptr, bias);
}

// round 10
// speedup vs baseline: 4.8577x; 1.0114x over previous
#include <cuda_runtime.h>
#include <cuda_fp16.h>
#include <stdint.h>

// ============================================================================
// SparseGradLinear, fully fp16 tensor-core pipeline (fp32 accumulate):
//   h   = threshold(fp16(x) @ fp16(U)^T)        [32768, 768]
//   out = fp16(h) @ fp16(VT @ weight)^T + bias  [32768, 768]
// R10: 4-stage cp.async pipeline, prefetch distance 3, ONE barrier per chunk
// (the top barrier already orders compute(c-1) before overwriting its stage).
// ============================================================================

#define DIM    768
#define MROWS  32768

__device__ __half g_x0[(size_t)MROWS * DIM];
__device__ __half g_h0[(size_t)MROWS * DIM];
__device__ __half g_u0[DIM * DIM];
__device__ __half g_w20[DIM * DIM];
__device__ float  g_w2part[4][DIM * DIM];

// ---- helpers ----
__device__ __forceinline__ uint32_t smem_u32(const void* p) {
    uint32_t a;
    asm("{ .reg .u64 t; cvta.to.shared.u64 t, %1; cvt.u32.u64 %0, t; }"
        : "=r"(a) : "l"(p));
    return a;
}
__device__ __forceinline__ void cp16(uint32_t dst, const void* src) {
    asm volatile("cp.async.cg.shared.global [%0], [%1], 16;" :: "r"(dst), "l"(src));
}
__device__ __forceinline__ void ldsm4(uint32_t* r, uint32_t addr) {
    asm volatile("ldmatrix.sync.aligned.m8n8.x4.shared.b16 {%0,%1,%2,%3}, [%4];"
                 : "=r"(r[0]), "=r"(r[1]), "=r"(r[2]), "=r"(r[3]) : "r"(addr));
}
__device__ __forceinline__ void mma16816(float* d, const uint32_t* a,
                                         uint32_t b0, uint32_t b1) {
    asm volatile(
        "mma.sync.aligned.m16n8k16.row.col.f32.f16.f16.f32 "
        "{%0,%1,%2,%3}, {%4,%5,%6,%7}, {%8,%9}, {%0,%1,%2,%3};"
        : "+f"(d[0]), "+f"(d[1]), "+f"(d[2]), "+f"(d[3])
        : "r"(a[0]), "r"(a[1]), "r"(a[2]), "r"(a[3]), "r"(b0), "r"(b1));
}

// ============================================================================
// Tensor-core NT GEMM: C[M,N] = A[M,K] @ B[N,K]^T, single fp16 product.
// CTA 128x128, BK=32, 256 thr (8 warps, 2m x 4n, warp tile 64x32),
// 4-stage cp.async pipeline (prefetch distance 3), 80B padded rows.
// MODE 0: threshold |v|>1e-3, fp16 H out.   MODE 1: +bias, fp32 out.
// ============================================================================
#define NCHUNK 24            // 768 / 32
#define BKB    64            // bytes of K per chunk-row (32 fp16)
#define ROWB   80            // padded row stride in bytes
#define MATB   (128 * ROWB)  // 10240 per operand tile
#define NSTAGE 4
#define STB    (2 * MATB)    // A + B per stage = 20480
#define GEMM_SMEM (NSTAGE * STB)   // 81920 -> 2 CTAs/SM

template <int MODE>
__global__ void __launch_bounds__(256, 2)
gemm_mma(const __half* __restrict__ A0, const __half* __restrict__ B0,
         float* __restrict__ outF, __half* __restrict__ H,
         const float* __restrict__ bias)
{
    extern __shared__ char smem[];
    const uint32_t sb = smem_u32(smem);

    const int tid  = threadIdx.x;
    const int lane = tid & 31;
    const int wid  = tid >> 5;
    const int wm   = wid >> 2;
    const int wn   = wid & 3;
    const int bm   = blockIdx.y * 128;
    const int bn   = blockIdx.x * 128;

    const int lrow = tid >> 1;
    const int lqB  = (tid & 1) * 32;
    const char* gA0 = (const char*)(A0 + (size_t)(bm + lrow) * DIM) + lqB;
    const char* gB0 = (const char*)(B0 + (size_t)(bn + lrow) * DIM) + lqB;
    const uint32_t sdst = lrow * ROWB + lqB;

    auto load_chunk = [&](int c) {
        const uint32_t st = sb + (c % NSTAGE) * STB + sdst;
        const int kb = c * BKB;
        cp16(st,            gA0 + kb); cp16(st + 16,        gA0 + kb + 16);
        cp16(st + MATB,     gB0 + kb); cp16(st + MATB + 16, gB0 + kb + 16);
        asm volatile("cp.async.commit_group;" ::: "memory");
    };

    const int lr8 = ((lane >> 3) & 1) * 8 + (lane & 7);
    const int lcb = ((lane >> 4) & 1) * 16;
    const uint32_t aRow = wm * 64 + lr8;
    const uint32_t bRow = wn * 32 + lr8;

    float acc[4][4][4];
#pragma unroll
    for (int i = 0; i < 4; i++)
#pragma unroll
        for (int j = 0; j < 4; j++)
#pragma unroll
            for (int k = 0; k < 4; k++) acc[i][j][k] = 0.0f;

    load_chunk(0);
    load_chunk(1);
    load_chunk(2);

    for (int c = 0; c < NCHUNK; c++) {
        // Chunk c must be resident; up to min(2, 23-c) newer groups may stay
        // pending (chunk c+3 is issued only after this wait+sync).
        const int rem = NCHUNK - 1 - c;
        if (rem >= 2)      asm volatile("cp.async.wait_group 2;" ::: "memory");
        else if (rem == 1) asm volatile("cp.async.wait_group 1;" ::: "memory");
        else               asm volatile("cp.async.wait_group 0;" ::: "memory");
        // Single barrier: makes chunk c visible CTA-wide AND proves every warp
        // finished compute(c-1), so its stage ((c+3)%4) is free to overwrite.
        __syncthreads();

        if (c + 3 < NCHUNK) load_chunk(c + 3);

        const uint32_t stg = sb + (c % NSTAGE) * STB;
#pragma unroll
        for (int ks = 0; ks < 2; ks++) {
            uint32_t af[4][4], bf[2][4];
#pragma unroll
            for (int mt = 0; mt < 4; mt++)
                ldsm4(af[mt], stg + (aRow + mt * 16) * ROWB + ks * 32 + lcb);
#pragma unroll
            for (int ng = 0; ng < 2; ng++)
                ldsm4(bf[ng], stg + MATB + (bRow + ng * 16) * ROWB + ks * 32 + lcb);

#pragma unroll
            for (int mt = 0; mt < 4; mt++)
#pragma unroll
                for (int nt = 0; nt < 4; nt++) {
                    const int ng = nt >> 1, p = nt & 1;
                    mma16816(acc[mt][nt], af[mt], bf[ng][p], bf[ng][p + 2]);
                }
        }
    }

    // ---- epilogue ----
    const int r0 = bm + wm * 64 + (lane >> 2);
    const int c0 = bn + wn * 32 + (lane & 3) * 2;
#pragma unroll
    for (int mt = 0; mt < 4; mt++) {
#pragma unroll
        for (int nt = 0; nt < 4; nt++) {
            const int col = c0 + nt * 8;
#pragma unroll
            for (int half = 0; half < 2; half++) {
                const int row = r0 + mt * 16 + half * 8;
                float vx = acc[mt][nt][half * 2];
                float vy = acc[mt][nt][half * 2 + 1];
                if (MODE == 0) {
                    vx = (fabsf(vx) > 1e-3f) ? vx : 0.0f;
                    vy = (fabsf(vy) > 1e-3f) ? vy : 0.0f;
                    __half2 hv;
                    hv.x = __float2half_rn(vx);
                    hv.y = __float2half_rn(vy);
                    *(__half2*)(H + (size_t)row * DIM + col) = hv;
                } else {
                    const float2 bb = *(const float2*)&bias[col];
                    float2 v = make_float2(vx + bb.x, vy + bb.y);
                    *(float2*)(outF + (size_t)row * DIM + col) = v;
                }
            }
        }
    }
}

// ============================================================================
// Elementwise fp32 -> fp16 convert, float4-vectorized.
// ============================================================================
__global__ void convert_fp16(const float4* __restrict__ src,
                             __half* __restrict__ dst, int n4)
{
    int i = blockIdx.x * blockDim.x + threadIdx.x;
    if (i >= n4) return;
    float4 v = src[i];
    __half2 a, b;
    a.x = __float2half_rn(v.x); a.y = __float2half_rn(v.y);
    b.x = __float2half_rn(v.z); b.y = __float2half_rn(v.w);
    __half2* p = (__half2*)(dst + (size_t)i * 4);
    p[0] = a; p[1] = b;
}

// ============================================================================
// W2 prep, split-K: partial[z] = VT[:, zK..] @ weight[zK.., :] over K/4=192.
// Reduce sums 4 partials -> single fp16. Deterministic (no atomics).
// ============================================================================
__global__ void __launch_bounds__(256)
gemm_nn_part(const float* __restrict__ A, const float* __restrict__ B,
             float* __restrict__ Cpart, int N, int K)
{
    constexpr int BK = 16;
    __shared__ float As[BK][68];
    __shared__ float Bs[BK][64];

    const int bp = blockIdx.y * 64;
    const int bc = blockIdx.x * 64;
    const int kz = blockIdx.z;
    const int kbeg = kz * (K / 4);
    const int kend = kbeg + (K / 4);
    float* C = Cpart + (size_t)kz * N * N;

    const int t  = threadIdx.x;
    const int tx = t & 15;
    const int ty = t >> 4;

    float acc[4][4] = {};

    for (int k0 = kbeg; k0 < kend; k0 += BK) {
        {
            const int r = t >> 2;
            const int o4 = (t & 3) * 4;
            float4 av = *(const float4*)(A + (size_t)(bp + r) * K + k0 + o4);
            As[o4 + 0][r] = av.x; As[o4 + 1][r] = av.y;
            As[o4 + 2][r] = av.z; As[o4 + 3][r] = av.w;
        }
        {
            const int o  = t >> 4;
            const int c4 = (t & 15) * 4;
            *(float4*)&Bs[o][c4] = *(const float4*)(B + (size_t)(k0 + o) * N + bc + c4);
        }
        __syncthreads();
#pragma unroll
        for (int o = 0; o < BK; o++) {
            float a[4], b[4];
#pragma unroll
            for (int i = 0; i < 4; i++) a[i] = As[o][ty * 4 + i];
#pragma unroll
            for (int j = 0; j < 4; j++) b[j] = Bs[o][tx * 4 + j];
#pragma unroll
            for (int i = 0; i < 4; i++)
#pragma unroll
                for (int j = 0; j < 4; j++) acc[i][j] += a[i] * b[j];
        }
        __syncthreads();
    }

#pragma unroll
    for (int i = 0; i < 4; i++)
#pragma unroll
        for (int j = 0; j < 4; j++)
            C[(size_t)(bp + ty * 4 + i) * N + bc + tx * 4 + j] = acc[i][j];
}

__global__ void reduce_w2(const float* __restrict__ Cpart,
                          __half* __restrict__ C0, int n)
{
    int i = blockIdx.x * blockDim.x + threadIdx.x;
    if (i >= n) return;
    float v = Cpart[i] + Cpart[i + n] + Cpart[i + 2 * n] + Cpart[i + 3 * n];
    C0[i] = __float2half_rn(v);
}

// ============================================================================
// kernel_launch — inputs: x, weight, bias, U, VT; output fp32 [32768,768]
// ============================================================================
extern "C" void kernel_launch(void* const* d_in, const int* in_sizes, int n_in,
                              void* d_out, int out_size)
{
    const float* x      = (const float*)d_in[0];
    const float* weight = (const float*)d_in[1];
    const float* bias   = (const float*)d_in[2];
    const float* U      = (const float*)d_in[3];
    const float* VT     = (const float*)d_in[4];
    float* out          = (float*)d_out;

    __half *x0, *h0, *u0, *w20;
    float* w2p;
    cudaGetSymbolAddress((void**)&x0,  g_x0);
    cudaGetSymbolAddress((void**)&h0,  g_h0);
    cudaGetSymbolAddress((void**)&u0,  g_u0);
    cudaGetSymbolAddress((void**)&w20, g_w20);
    cudaGetSymbolAddress((void**)&w2p, g_w2part);

    cudaFuncSetAttribute(gemm_mma<0>, cudaFuncAttributeMaxDynamicSharedMemorySize, GEMM_SMEM);
    cudaFuncSetAttribute(gemm_mma<1>, cudaFuncAttributeMaxDynamicSharedMemorySize, GEMM_SMEM);

    const int M = in_sizes[0] / DIM;   // 32768

    {
        int n4 = M * DIM / 4;
        convert_fp16<<<(n4 + 255) / 256, 256>>>((const float4*)x, x0, n4);
    }
    {
        int n4 = DIM * DIM / 4;
        convert_fp16<<<(n4 + 255) / 256, 256>>>((const float4*)U, u0, n4);
    }
    // W2 = VT @ weight via split-K partials, reduced to single fp16.
    gemm_nn_part<<<dim3(DIM / 64, DIM / 64, 4), 256>>>(VT, weight, w2p, DIM, DIM);
    {
        int n = DIM * DIM;
        reduce_w2<<<(n + 255) / 256, 256>>>(w2p, w20, n);
    }

    // GEMM1: h = threshold(x0 @ u0^T) -> fp16 h0
    gemm_mma<0><<<dim3(DIM / 128, M / 128), 256, GEMM_SMEM>>>(
        x0, u0, nullptr, h0, nullptr);
    // GEMM2: out = h0 @ w20^T + bias
    gemm_mma<1><<<dim3(DIM / 128, M / 128), 256, GEMM_SMEM>>>(
        h0, w20, out, nullptr, bias);
}

// round 11
// speedup vs baseline: 5.0557x; 1.0408x over previous
#include <cuda_runtime.h>
#include <cuda_fp16.h>
#include <stdint.h>

// ============================================================================
// SparseGradLinear, fully fp16 tensor-core pipeline (fp32 accumulate):
//   h   = threshold(fp16(x) @ fp16(U)^T)        [32768, 768]
//   out = fp16(h) @ fp16(VT @ weight)^T + bias  [32768, 768]
// R11: GEMM1+GEMM2 FUSED into one kernel. Phase-1 CTAs (bid<NT1) produce h
// tiles and release ready[mb]; phase-2 CTAs acquire-spin until ready[mb]==6.
// Producers all have lower bids than consumers -> no deadlock; consumers
// backfill the producer tail wave.
// ============================================================================

#define DIM    768
#define MROWS  32768
#define MBLKS  (MROWS / 128)   // 256
#define NBLKS  (DIM / 128)     // 6
#define NT1    (MBLKS * NBLKS) // 1536 phase-1 tiles

__device__ __half    g_x0[(size_t)MROWS * DIM];
__device__ __half    g_h0[(size_t)MROWS * DIM];
__device__ __half    g_u0[DIM * DIM];
__device__ __half    g_w20[DIM * DIM];
__device__ float     g_w2part[4][DIM * DIM];
__device__ unsigned  g_ready[MBLKS];

// ---- helpers ----
__device__ __forceinline__ uint32_t smem_u32(const void* p) {
    uint32_t a;
    asm("{ .reg .u64 t; cvta.to.shared.u64 t, %1; cvt.u32.u64 %0, t; }"
        : "=r"(a) : "l"(p));
    return a;
}
__device__ __forceinline__ void cp16(uint32_t dst, const void* src) {
    asm volatile("cp.async.cg.shared.global [%0], [%1], 16;" :: "r"(dst), "l"(src));
}
__device__ __forceinline__ void ldsm4(uint32_t* r, uint32_t addr) {
    asm volatile("ldmatrix.sync.aligned.m8n8.x4.shared.b16 {%0,%1,%2,%3}, [%4];"
                 : "=r"(r[0]), "=r"(r[1]), "=r"(r[2]), "=r"(r[3]) : "r"(addr));
}
__device__ __forceinline__ void mma16816(float* d, const uint32_t* a,
                                         uint32_t b0, uint32_t b1) {
    asm volatile(
        "mma.sync.aligned.m16n8k16.row.col.f32.f16.f16.f32 "
        "{%0,%1,%2,%3}, {%4,%5,%6,%7}, {%8,%9}, {%0,%1,%2,%3};"
        : "+f"(d[0]), "+f"(d[1]), "+f"(d[2]), "+f"(d[3])
        : "r"(a[0]), "r"(a[1]), "r"(a[2]), "r"(a[3]), "r"(b0), "r"(b1));
}

// ============================================================================
// Fused dual-phase tensor-core NT GEMM.
// Phase 1 (bid < NT1):  h_tile = threshold(x @ U^T), fp16; release ready[mb].
// Phase 2 (bid >= NT1): out_tile = h @ W2^T + bias, fp32; acquire ready[mb].
// CTA 128x128, BK=32, 256 thr, 4-stage cp.async pipeline, 80B padded rows.
// ============================================================================
#define NCHUNK 24            // 768 / 32
#define BKB    64            // bytes of K per chunk-row (32 fp16)
#define ROWB   80            // padded row stride in bytes
#define MATB   (128 * ROWB)  // 10240 per operand tile
#define NSTAGE 4
#define STB    (2 * MATB)    // A + B per stage = 20480
#define GEMM_SMEM (NSTAGE * STB)   // 81920 -> 2 CTAs/SM

__global__ void __launch_bounds__(256, 2)
fused_gemm(const __half* __restrict__ X, const __half* __restrict__ U,
           const __half* __restrict__ W2,
           __half* __restrict__ H, float* __restrict__ outF,
           const float* __restrict__ bias)
{
    extern __shared__ char smem[];
    const uint32_t sb = smem_u32(smem);

    const int bid = blockIdx.x;
    const bool ph2 = (bid >= NT1);
    const int idx = ph2 ? bid - NT1 : bid;
    const int mb = idx / NBLKS;         // row block 0..255
    const int nb = idx % NBLKS;         // col block 0..5
    const int bm = mb * 128;
    const int bn = nb * 128;

    const int tid  = threadIdx.x;
    const int lane = tid & 31;
    const int wid  = tid >> 5;
    const int wm   = wid >> 2;
    const int wn   = wid & 3;

    // Phase-2: wait until all 6 producer tiles of row-block mb are done.
    if (ph2) {
        if (tid == 0) {
            unsigned v;
            while (true) {
                asm volatile("ld.acquire.gpu.global.u32 %0, [%1];"
                             : "=r"(v) : "l"(g_ready + mb) : "memory");
                if (v >= NBLKS) break;
                __nanosleep(200);
            }
        }
        __syncthreads();
    }

    const __half* A0 = ph2 ? H  : X;
    const __half* B0 = ph2 ? W2 : U;

    const int lrow = tid >> 1;
    const int lqB  = (tid & 1) * 32;
    const char* gA0 = (const char*)(A0 + (size_t)(bm + lrow) * DIM) + lqB;
    const char* gB0 = (const char*)(B0 + (size_t)(bn + lrow) * DIM) + lqB;
    const uint32_t sdst = lrow * ROWB + lqB;

    auto load_chunk = [&](int c) {
        const uint32_t st = sb + (c % NSTAGE) * STB + sdst;
        const int kb = c * BKB;
        cp16(st,            gA0 + kb); cp16(st + 16,        gA0 + kb + 16);
        cp16(st + MATB,     gB0 + kb); cp16(st + MATB + 16, gB0 + kb + 16);
        asm volatile("cp.async.commit_group;" ::: "memory");
    };

    const int lr8 = ((lane >> 3) & 1) * 8 + (lane & 7);
    const int lcb = ((lane >> 4) & 1) * 16;
    const uint32_t aRow = wm * 64 + lr8;
    const uint32_t bRow = wn * 32 + lr8;

    float acc[4][4][4];
#pragma unroll
    for (int i = 0; i < 4; i++)
#pragma unroll
        for (int j = 0; j < 4; j++)
#pragma unroll
            for (int k = 0; k < 4; k++) acc[i][j][k] = 0.0f;

    load_chunk(0);
    load_chunk(1);
    load_chunk(2);

    for (int c = 0; c < NCHUNK; c++) {
        const int rem = NCHUNK - 1 - c;
        if (rem >= 2)      asm volatile("cp.async.wait_group 2;" ::: "memory");
        else if (rem == 1) asm volatile("cp.async.wait_group 1;" ::: "memory");
        else               asm volatile("cp.async.wait_group 0;" ::: "memory");
        // Single barrier: chunk c visible CTA-wide AND every warp finished
        // compute(c-1), so stage ((c+3)%4) is free to overwrite.
        __syncthreads();

        if (c + 3 < NCHUNK) load_chunk(c + 3);

        const uint32_t stg = sb + (c % NSTAGE) * STB;
#pragma unroll
        for (int ks = 0; ks < 2; ks++) {
            uint32_t af[4][4], bf[2][4];
#pragma unroll
            for (int mt = 0; mt < 4; mt++)
                ldsm4(af[mt], stg + (aRow + mt * 16) * ROWB + ks * 32 + lcb);
#pragma unroll
            for (int ng = 0; ng < 2; ng++)
                ldsm4(bf[ng], stg + MATB + (bRow + ng * 16) * ROWB + ks * 32 + lcb);

#pragma unroll
            for (int mt = 0; mt < 4; mt++)
#pragma unroll
                for (int nt = 0; nt < 4; nt++) {
                    const int ng = nt >> 1, p = nt & 1;
                    mma16816(acc[mt][nt], af[mt], bf[ng][p], bf[ng][p + 2]);
                }
        }
    }

    // ---- epilogue ----
    const int r0 = bm + wm * 64 + (lane >> 2);
    const int c0 = bn + wn * 32 + (lane & 3) * 2;
    if (!ph2) {
#pragma unroll
        for (int mt = 0; mt < 4; mt++)
#pragma unroll
            for (int nt = 0; nt < 4; nt++) {
                const int col = c0 + nt * 8;
#pragma unroll
                for (int half = 0; half < 2; half++) {
                    const int row = r0 + mt * 16 + half * 8;
                    float vx = acc[mt][nt][half * 2];
                    float vy = acc[mt][nt][half * 2 + 1];
                    vx = (fabsf(vx) > 1e-3f) ? vx : 0.0f;
                    vy = (fabsf(vy) > 1e-3f) ? vy : 0.0f;
                    __half2 hv;
                    hv.x = __float2half_rn(vx);
                    hv.y = __float2half_rn(vy);
                    *(__half2*)(H + (size_t)row * DIM + col) = hv;
                }
            }
        // Release: h tile globally visible, then count this producer.
        __syncthreads();
        if (tid == 0)
            asm volatile("red.release.gpu.global.add.u32 [%0], 1;"
                         :: "l"(g_ready + mb) : "memory");
    } else {
#pragma unroll
        for (int mt = 0; mt < 4; mt++)
#pragma unroll
            for (int nt = 0; nt < 4; nt++) {
                const int col = c0 + nt * 8;
#pragma unroll
                for (int half = 0; half < 2; half++) {
                    const int row = r0 + mt * 16 + half * 8;
                    const float2 bb = *(const float2*)&bias[col];
                    float2 v = make_float2(acc[mt][nt][half * 2] + bb.x,
                                           acc[mt][nt][half * 2 + 1] + bb.y);
                    *(float2*)(outF + (size_t)row * DIM + col) = v;
                }
            }
    }
}

// ============================================================================
// Flag reset (graph-replay safe; runs before fused kernel each call).
// ============================================================================
__global__ void zero_flags()
{
    if (threadIdx.x < MBLKS) g_ready[threadIdx.x] = 0;
}

// ============================================================================
// Elementwise fp32 -> fp16 convert, float4-vectorized.
// ============================================================================
__global__ void convert_fp16(const float4* __restrict__ src,
                             __half* __restrict__ dst, int n4)
{
    int i = blockIdx.x * blockDim.x + threadIdx.x;
    if (i >= n4) return;
    float4 v = src[i];
    __half2 a, b;
    a.x = __float2half_rn(v.x); a.y = __float2half_rn(v.y);
    b.x = __float2half_rn(v.z); b.y = __float2half_rn(v.w);
    __half2* p = (__half2*)(dst + (size_t)i * 4);
    p[0] = a; p[1] = b;
}

// ============================================================================
// W2 prep, split-K: partial[z] = VT[:, zK..] @ weight[zK.., :] over K/4=192.
// Reduce sums 4 partials -> single fp16. Deterministic (no atomics).
// ============================================================================
__global__ void __launch_bounds__(256)
gemm_nn_part(const float* __restrict__ A, const float* __restrict__ B,
             float* __restrict__ Cpart, int N, int K)
{
    constexpr int BK = 16;
    __shared__ float As[BK][68];
    __shared__ float Bs[BK][64];

    const int bp = blockIdx.y * 64;
    const int bc = blockIdx.x * 64;
    const int kz = blockIdx.z;
    const int kbeg = kz * (K / 4);
    const int kend = kbeg + (K / 4);
    float* C = Cpart + (size_t)kz * N * N;

    const int t  = threadIdx.x;
    const int tx = t & 15;
    const int ty = t >> 4;

    float acc[4][4] = {};

    for (int k0 = kbeg; k0 < kend; k0 += BK) {
        {
            const int r = t >> 2;
            const int o4 = (t & 3) * 4;
            float4 av = *(const float4*)(A + (size_t)(bp + r) * K + k0 + o4);
            As[o4 + 0][r] = av.x; As[o4 + 1][r] = av.y;
            As[o4 + 2][r] = av.z; As[o4 + 3][r] = av.w;
        }
        {
            const int o  = t >> 4;
            const int c4 = (t & 15) * 4;
            *(float4*)&Bs[o][c4] = *(const float4*)(B + (size_t)(k0 + o) * N + bc + c4);
        }
        __syncthreads();
#pragma unroll
        for (int o = 0; o < BK; o++) {
            float a[4], b[4];
#pragma unroll
            for (int i = 0; i < 4; i++) a[i] = As[o][ty * 4 + i];
#pragma unroll
            for (int j = 0; j < 4; j++) b[j] = Bs[o][tx * 4 + j];
#pragma unroll
            for (int i = 0; i < 4; i++)
#pragma unroll
                for (int j = 0; j < 4; j++) acc[i][j] += a[i] * b[j];
        }
        __syncthreads();
    }

#pragma unroll
    for (int i = 0; i < 4; i++)
#pragma unroll
        for (int j = 0; j < 4; j++)
            C[(size_t)(bp + ty * 4 + i) * N + bc + tx * 4 + j] = acc[i][j];
}

__global__ void reduce_w2(const float* __restrict__ Cpart,
                          __half* __restrict__ C0, int n)
{
    int i = blockIdx.x * blockDim.x + threadIdx.x;
    if (i >= n) return;
    float v = Cpart[i] + Cpart[i + n] + Cpart[i + 2 * n] + Cpart[i + 3 * n];
    C0[i] = __float2half_rn(v);
}

// ============================================================================
// kernel_launch — inputs: x, weight, bias, U, VT; output fp32 [32768,768]
// ============================================================================
extern "C" void kernel_launch(void* const* d_in, const int* in_sizes, int n_in,
                              void* d_out, int out_size)
{
    const float* x      = (const float*)d_in[0];
    const float* weight = (const float*)d_in[1];
    const float* bias   = (const float*)d_in[2];
    const float* U      = (const float*)d_in[3];
    const float* VT     = (const float*)d_in[4];
    float* out          = (float*)d_out;

    __half *x0, *h0, *u0, *w20;
    float* w2p;
    cudaGetSymbolAddress((void**)&x0,  g_x0);
    cudaGetSymbolAddress((void**)&h0,  g_h0);
    cudaGetSymbolAddress((void**)&u0,  g_u0);
    cudaGetSymbolAddress((void**)&w20, g_w20);
    cudaGetSymbolAddress((void**)&w2p, g_w2part);

    cudaFuncSetAttribute(fused_gemm, cudaFuncAttributeMaxDynamicSharedMemorySize, GEMM_SMEM);

    const int M = in_sizes[0] / DIM;   // 32768

    zero_flags<<<1, 256>>>();
    {
        int n4 = M * DIM / 4;
        convert_fp16<<<(n4 + 255) / 256, 256>>>((const float4*)x, x0, n4);
    }
    {
        int n4 = DIM * DIM / 4;
        convert_fp16<<<(n4 + 255) / 256, 256>>>((const float4*)U, u0, n4);
    }
    // W2 = VT @ weight via split-K partials, reduced to single fp16.
    gemm_nn_part<<<dim3(DIM / 64, DIM / 64, 4), 256>>>(VT, weight, w2p, DIM, DIM);
    {
        int n = DIM * DIM;
        reduce_w2<<<(n + 255) / 256, 256>>>(w2p, w20, n);
    }

    // Fused GEMM1 (tiles 0..NT1-1) + GEMM2 (tiles NT1..2*NT1-1) with
    // per-row-block acquire/release dataflow sync on g_ready.
    fused_gemm<<<2 * NT1, 256, GEMM_SMEM>>>(x0, u0, w20, h0, out, bias);
}